// round 15
// baseline (speedup 1.0000x reference)
#include <cuda_runtime.h>
#include <cuda_fp16.h>
#include <math.h>
#include <mma.h>
#include <stdint.h>

using namespace nvcuda;

// Problem constants
#define Bn 16
#define Nn 512
#define Dn 256
#define Hn 8
#define Ln 4
#define DKn 32

#define BND (Bn*Nn*Dn)   // 2,097,152
#define BNN (Bn*Nn*Nn)   // 4,194,304
#define WSZ (Ln*Dn*Dn)   // 262,144 per weight set

static __device__ float  g_x[BND];
static __device__ __half g_baseh[BNN];
static __device__ __half g_hh[BND];
static __device__ __half g_qh[BND];
static __device__ __half g_kh[BND];
static __device__ __half g_vh[BND];
static __device__ __half g_t1[BND];
static __device__ __half g_ph[BND];      // attention output (half)
static __device__ __half g_wh[6 * WSZ];
static __device__ int    g_idx[Bn * Nn];
static __device__ int    g_cnt[Bn];

// ---------------------------------------------------------------------------
// helpers
// ---------------------------------------------------------------------------
__device__ __forceinline__ uint4 pack_h8(float4 a, float4 b) {
    half2 h0 = __floats2half2_rn(a.x, a.y);
    half2 h1 = __floats2half2_rn(a.z, a.w);
    half2 h2 = __floats2half2_rn(b.x, b.y);
    half2 h3 = __floats2half2_rn(b.z, b.w);
    uint4 r;
    r.x = *(unsigned*)&h0; r.y = *(unsigned*)&h1;
    r.z = *(unsigned*)&h2; r.w = *(unsigned*)&h3;
    return r;
}

__device__ __forceinline__ void storeC4h(half* p, float4 v) {
    half2 a = __floats2half2_rn(v.x, v.y);
    half2 b = __floats2half2_rn(v.z, v.w);
    uint2 u; u.x = *(unsigned*)&a; u.y = *(unsigned*)&b;
    *(uint2*)p = u;
}

// cp.async primitives
__device__ __forceinline__ void cp16(uint32_t s, const void* g) {
    asm volatile("cp.async.cg.shared.global [%0], [%1], 16;" :: "r"(s), "l"(g));
}
__device__ __forceinline__ void cp_commit() {
    asm volatile("cp.async.commit_group;" ::: "memory");
}
__device__ __forceinline__ void cp_wait1() {
    asm volatile("cp.async.wait_group 1;" ::: "memory");
}
__device__ __forceinline__ void cp_wait0() {
    asm volatile("cp.async.wait_group 0;" ::: "memory");
}

// ---------------------------------------------------------------------------
// weight conversion fp32 -> fp16
// ---------------------------------------------------------------------------
__global__ void cvt_w(const float* __restrict__ Wq, const float* __restrict__ Wk,
                      const float* __restrict__ Wv, const float* __restrict__ Wo,
                      const float* __restrict__ Wf1, const float* __restrict__ Wf2,
                      __half* __restrict__ out) {
    const int idx = (blockIdx.x * 256 + threadIdx.x) * 4;
    const int w = idx / WSZ;
    const int r = idx - w * WSZ;
    const float* srcs[6] = {Wq, Wk, Wv, Wo, Wf1, Wf2};
    float4 v = *(const float4*)(srcs[w] + r);
    half2 a = __floats2half2_rn(v.x, v.y);
    half2 b = __floats2half2_rn(v.z, v.w);
    uint2 u; u.x = *(unsigned*)&a; u.y = *(unsigned*)&b;
    *(uint2*)(out + idx) = u;
}

// ---------------------------------------------------------------------------
// mask compaction
// ---------------------------------------------------------------------------
__global__ void mask_idx_kernel(const int* __restrict__ mask,
                                int* __restrict__ idx, int* __restrict__ cnt) {
    __shared__ int sc[512];
    const int b = blockIdx.x, t = threadIdx.x;
    const int m = (mask[b * Nn + t] != 0) ? 1 : 0;
    sc[t] = m;
    __syncthreads();
    for (int o = 1; o < 512; o <<= 1) {
        int v = (t >= o) ? sc[t - o] : 0;
        __syncthreads();
        sc[t] += v;
        __syncthreads();
    }
    if (m) idx[b * Nn + sc[t] - 1] = t;
    if (t == 511) cnt[b] = sc[511];
}

// ---------------------------------------------------------------------------
// block reductions (256 threads)
// ---------------------------------------------------------------------------
__device__ __forceinline__ float blockSum256(float v) {
    __shared__ float sm[8];
    __syncthreads();
    #pragma unroll
    for (int o = 16; o; o >>= 1) v += __shfl_xor_sync(0xffffffffu, v, o);
    if ((threadIdx.x & 31) == 0) sm[threadIdx.x >> 5] = v;
    __syncthreads();
    float t = 0.f;
    #pragma unroll
    for (int i = 0; i < 8; i++) t += sm[i];
    return t;
}

__device__ __forceinline__ float blockMax256(float v) {
    __shared__ float sm[8];
    __syncthreads();
    #pragma unroll
    for (int o = 16; o; o >>= 1) v = fmaxf(v, __shfl_xor_sync(0xffffffffu, v, o));
    if ((threadIdx.x & 31) == 0) sm[threadIdx.x >> 5] = v;
    __syncthreads();
    float t = sm[0];
    #pragma unroll
    for (int i = 1; i < 8; i++) t = fmaxf(t, sm[i]);
    return t;
}

// ---------------------------------------------------------------------------
// base (half output)
// ---------------------------------------------------------------------------
__global__ void base_kernel(const float* __restrict__ dist,
                            const float* __restrict__ adj,
                            const int*   __restrict__ mask,
                            __half* __restrict__ base) {
    const int bi = blockIdx.x;
    const int b  = bi >> 9;
    const float* dr = dist + (size_t)bi * Nn;
    const float* ar = adj  + (size_t)bi * Nn;
    __half*      br = base + (size_t)bi * Nn;
    const int t = threadIdx.x;

    const int m0 = mask[b * Nn + t];
    const int m1 = mask[b * Nn + t + 256];
    float v0 = m0 ? -dr[t]       : -INFINITY;
    float v1 = m1 ? -dr[t + 256] : -INFINITY;

    float mx = blockMax256(fmaxf(v0, v1));
    float e0 = __expf(v0 - mx);
    float e1 = __expf(v1 - mx);
    float ssum = blockSum256(e0 + e1);

    float a0 = ar[t], a1 = ar[t + 256];
    float asum = blockSum256(a0 + a1);

    float cs = 0.3f / ssum;
    float ca = 0.4f / (asum + 1e-6f);
    br[t]       = __float2half_rn(e0 * cs + a0 * ca);
    br[t + 256] = __float2half_rn(e1 * cs + a1 * ca);
}

// ---------------------------------------------------------------------------
// LayerNorm (ddof=1), warp per row
// ---------------------------------------------------------------------------
__device__ __forceinline__ void ln_core(const float* __restrict__ xr,
                                        const float* __restrict__ a,
                                        const float* __restrict__ bb,
                                        int c, float4& o0, float4& o1) {
    float4 v0 = *(const float4*)(xr + c);
    float4 v1 = *(const float4*)(xr + c + 4);
    float s = v0.x+v0.y+v0.z+v0.w + v1.x+v1.y+v1.z+v1.w;
    #pragma unroll
    for (int o = 16; o; o >>= 1) s += __shfl_xor_sync(0xffffffffu, s, o);
    float mean = s * (1.f / Dn);

    float c0[8] = {v0.x-mean, v0.y-mean, v0.z-mean, v0.w-mean,
                   v1.x-mean, v1.y-mean, v1.z-mean, v1.w-mean};
    float sq = 0.f;
    #pragma unroll
    for (int i = 0; i < 8; i++) sq += c0[i]*c0[i];
    #pragma unroll
    for (int o = 16; o; o >>= 1) sq += __shfl_xor_sync(0xffffffffu, sq, o);
    float inv = 1.f / (sqrtf(sq * (1.f / (Dn - 1))) + 1e-6f);

    float4 a0 = *(const float4*)(a + c);
    float4 a1 = *(const float4*)(a + c + 4);
    float4 b0 = *(const float4*)(bb + c);
    float4 b1 = *(const float4*)(bb + c + 4);
    o0.x = a0.x*c0[0]*inv + b0.x;  o0.y = a0.y*c0[1]*inv + b0.y;
    o0.z = a0.z*c0[2]*inv + b0.z;  o0.w = a0.w*c0[3]*inv + b0.w;
    o1.x = a1.x*c0[4]*inv + b1.x;  o1.y = a1.y*c0[5]*inv + b1.y;
    o1.z = a1.z*c0[6]*inv + b1.z;  o1.w = a1.w*c0[7]*inv + b1.w;
}

__global__ void ln_f(const float* __restrict__ x, const float* __restrict__ a,
                     const float* __restrict__ bb, float* __restrict__ out) {
    const size_t row = (size_t)blockIdx.x * 8 + (threadIdx.x >> 5);
    const int c = (threadIdx.x & 31) * 8;
    float4 o0, o1;
    ln_core(x + row * Dn, a, bb, c, o0, o1);
    *(float4*)(out + row * Dn + c)     = o0;
    *(float4*)(out + row * Dn + c + 4) = o1;
}

__global__ void ln_h(const float* __restrict__ x, const float* __restrict__ a,
                     const float* __restrict__ bb, __half* __restrict__ out) {
    const size_t row = (size_t)blockIdx.x * 8 + (threadIdx.x >> 5);
    const int c = (threadIdx.x & 31) * 8;
    float4 o0, o1;
    ln_core(x + row * Dn, a, bb, c, o0, o1);
    *(uint4*)(out + row * Dn + c) = pack_h8(o0, o1);
}

// ---------------------------------------------------------------------------
// Shared epilogue for 64x128 body
// ---------------------------------------------------------------------------
#define LDS_ 36

template<int CHALF>
__device__ __forceinline__ void gemm_epilogue(
    wmma::fragment<wmma::accumulator, 16, 16, 16, float> acc[2][2],
    float* fst, const float* bias, const float* res, void* Cv,
    int Nc, int act, int tm, int tn, int warp, int lane, int wm, int wn) {

    float* stg = fst + warp * 32 * LDS_;
    #pragma unroll
    for (int mm = 0; mm < 2; mm++)
        #pragma unroll
        for (int nn = 0; nn < 2; nn++)
            wmma::store_matrix_sync(stg + mm * 16 * LDS_ + nn * 16,
                                    acc[mm][nn], LDS_, wmma::mem_row_major);
    __syncwarp();

    const int growb = tm + wm * 32;
    const int gcolb = tn + wn * 32;
    #pragma unroll
    for (int it = 0; it < 8; it++) {
        int idx = it * 32 + lane;
        int rr = idx >> 3;
        int cc = (idx & 7) * 4;
        int col = gcolb + cc;
        float4 v = *(float4*)(stg + rr * LDS_ + cc);
        if (bias) {
            float4 bb4 = *(const float4*)(bias + col);
            v.x += bb4.x; v.y += bb4.y; v.z += bb4.z; v.w += bb4.w;
        }
        if (act) {
            v.x = v.x > 0.f ? v.x : 0.1f * v.x;
            v.y = v.y > 0.f ? v.y : 0.1f * v.y;
            v.z = v.z > 0.f ? v.z : 0.1f * v.z;
            v.w = v.w > 0.f ? v.w : 0.1f * v.w;
        }
        size_t row = (size_t)(growb + rr);
        if (CHALF) {
            storeC4h((half*)Cv + row * Nc + col, v);
        } else {
            float* Cf = (float*)Cv;
            if (res) {
                float4 r4 = *(const float4*)(res + row * Nc + col);
                v.x += r4.x; v.y += r4.y; v.z += r4.z; v.w += r4.w;
            }
            *(float4*)(Cf + row * Nc + col) = v;
        }
    }
}

// ---------------------------------------------------------------------------
// cp.async 3-stage GEMM, 64x128 tile (256-block launches: Wo/f1/f2/baseV)
// ---------------------------------------------------------------------------
#define CA_SMEM_BYTES 41472

template<int CHALF>
__device__ __forceinline__ void gemm_body_ca(
    const half* __restrict__ A, const half* __restrict__ W,
    const float* __restrict__ bias, const float* __restrict__ res,
    void* __restrict__ Cv, int Nc, int K, int act, char* smemc) {

    half*  hs  = (half*)smemc;
    float* fst = (float*)smemc;

    const int tm = blockIdx.y * 64;
    const int tn = blockIdx.x * 128;
    const int tid = threadIdx.x;
    const int warp = tid >> 5;
    const int lane = tid & 31;
    const int wm = warp >> 2;
    const int wn = warp & 3;

    const int arow = tid >> 2;
    const int acol = (tid & 3) * 8;
    const uint32_t sbase = (uint32_t)__cvta_generic_to_shared(hs);

    const half* gA = A + (size_t)(tm + arow) * K + acol;

    wmma::fragment<wmma::accumulator, 16, 16, 16, float> acc[2][2];
    #pragma unroll
    for (int mm = 0; mm < 2; mm++)
        #pragma unroll
        for (int nn = 0; nn < 2; nn++)
            wmma::fill_fragment(acc[mm][nn], 0.f);

    const int nIter = K >> 5;

    #pragma unroll
    for (int p = 0; p < 2; p++) {
        int k0 = p * 32;
        cp16(sbase + (uint32_t)(p * 2560 + arow * 40 + acol) * 2, gA + k0);
        #pragma unroll
        for (int i = 0; i < 2; i++) {
            int idx = tid + i * 256;
            int r = idx >> 4, c = (idx & 15) * 8;
            cp16(sbase + (uint32_t)(7680 + p * 4352 + r * 136 + c) * 2,
                 W + (size_t)(k0 + r) * Nc + tn + c);
        }
        cp_commit();
    }

    int s = 0;
    for (int it = 0; it < nIter; it++) {
        if (it + 1 < nIter) cp_wait1(); else cp_wait0();
        __syncthreads();

        if (it + 2 < nIter) {
            int ps = (it + 2) % 3;
            int k0 = (it + 2) * 32;
            cp16(sbase + (uint32_t)(ps * 2560 + arow * 40 + acol) * 2, gA + k0);
            #pragma unroll
            for (int i = 0; i < 2; i++) {
                int idx = tid + i * 256;
                int r = idx >> 4, c = (idx & 15) * 8;
                cp16(sbase + (uint32_t)(7680 + ps * 4352 + r * 136 + c) * 2,
                     W + (size_t)(k0 + r) * Nc + tn + c);
            }
            cp_commit();
        }

        const half* As = hs + s * 2560;
        const half* Bs = hs + 7680 + s * 4352;
        #pragma unroll
        for (int ks = 0; ks < 2; ks++) {
            wmma::fragment<wmma::matrix_a, 16, 16, 16, half, wmma::row_major> af[2];
            wmma::fragment<wmma::matrix_b, 16, 16, 16, half, wmma::row_major> bf[2];
            wmma::load_matrix_sync(af[0], As + (wm * 32)      * 40 + ks * 16, 40);
            wmma::load_matrix_sync(af[1], As + (wm * 32 + 16) * 40 + ks * 16, 40);
            wmma::load_matrix_sync(bf[0], Bs + (ks * 16) * 136 + wn * 32,      136);
            wmma::load_matrix_sync(bf[1], Bs + (ks * 16) * 136 + wn * 32 + 16, 136);
            wmma::mma_sync(acc[0][0], af[0], bf[0], acc[0][0]);
            wmma::mma_sync(acc[0][1], af[0], bf[1], acc[0][1]);
            wmma::mma_sync(acc[1][0], af[1], bf[0], acc[1][0]);
            wmma::mma_sync(acc[1][1], af[1], bf[1], acc[1][1]);
        }
        s = (s == 2) ? 0 : s + 1;
    }
    __syncthreads();

    gemm_epilogue<CHALF>(acc, fst, bias, res, Cv, Nc, act, tm, tn, warp, lane, wm, wn);
}

__global__ void __launch_bounds__(256, 2)
gemm_hh(const half* __restrict__ A, const half* __restrict__ W,
        const float* __restrict__ bias, half* __restrict__ C,
        int Nc, int K, int act) {
    __shared__ __align__(16) char smem[CA_SMEM_BYTES];
    gemm_body_ca<1>(A, W, bias, nullptr, C, Nc, K, act, smem);
}

__global__ void __launch_bounds__(256, 2)
gemm_hf(const half* __restrict__ A, const half* __restrict__ W,
        const float* __restrict__ bias, const float* __restrict__ res,
        float* __restrict__ C, int Nc, int K, int act) {
    __shared__ __align__(16) char smem[CA_SMEM_BYTES];
    gemm_body_ca<0>(A, W, bias, res, C, Nc, K, act, smem);
}

__global__ void __launch_bounds__(256, 2)
gemm_hhz(const half* __restrict__ A, const half* __restrict__ W,
         half* __restrict__ C, int Nc, int K,
         long sA, long sW, long sC) {
    __shared__ __align__(16) char smem[CA_SMEM_BYTES];
    gemm_body_ca<1>(A + (size_t)blockIdx.z * sA, W + (size_t)blockIdx.z * sW,
                    nullptr, nullptr, C + (size_t)blockIdx.z * sC, Nc, K, 0, smem);
}

// ---------------------------------------------------------------------------
// cp.async 3-stage GEMM, 128x128 tile (qkv only, 384 blocks)
// ---------------------------------------------------------------------------
#define CA2_SMEM 56832

__device__ __forceinline__ void gemm_body2(
    const half* __restrict__ A, const half* __restrict__ W,
    const float* __restrict__ bias, half* __restrict__ C,
    int Nc, int K, half* hs) {

    float* fst = (float*)hs;

    const int tm = blockIdx.y * 128;
    const int tn = blockIdx.x * 128;
    const int tid = threadIdx.x;
    const int warp = tid >> 5;
    const int lane = tid & 31;
    const int wm = warp >> 1;
    const int wn = warp & 1;

    const int ar0 = tid >> 2;
    const int ac0 = (tid & 3) * 8;
    const uint32_t sbase = (uint32_t)__cvta_generic_to_shared(hs);

    const half* gA0 = A + (size_t)(tm + ar0) * K + ac0;
    const half* gA1 = gA0 + (size_t)64 * K;

    wmma::fragment<wmma::accumulator, 16, 16, 16, float> acc[2][4];
    #pragma unroll
    for (int mm = 0; mm < 2; mm++)
        #pragma unroll
        for (int nn = 0; nn < 4; nn++)
            wmma::fill_fragment(acc[mm][nn], 0.f);

    const int nIter = K >> 5;

    #pragma unroll
    for (int p = 0; p < 2; p++) {
        int k0 = p * 32;
        cp16(sbase + (uint32_t)(p * 5120 + ar0 * 40 + ac0) * 2, gA0 + k0);
        cp16(sbase + (uint32_t)(p * 5120 + (ar0 + 64) * 40 + ac0) * 2, gA1 + k0);
        #pragma unroll
        for (int i = 0; i < 2; i++) {
            int idx = tid + i * 256;
            int r = idx >> 4, c = (idx & 15) * 8;
            cp16(sbase + (uint32_t)(15360 + p * 4352 + r * 136 + c) * 2,
                 W + (size_t)(k0 + r) * Nc + tn + c);
        }
        cp_commit();
    }

    int s = 0;
    for (int it = 0; it < nIter; it++) {
        if (it + 1 < nIter) cp_wait1(); else cp_wait0();
        __syncthreads();

        if (it + 2 < nIter) {
            int ps = (it + 2) % 3;
            int k0 = (it + 2) * 32;
            cp16(sbase + (uint32_t)(ps * 5120 + ar0 * 40 + ac0) * 2, gA0 + k0);
            cp16(sbase + (uint32_t)(ps * 5120 + (ar0 + 64) * 40 + ac0) * 2, gA1 + k0);
            #pragma unroll
            for (int i = 0; i < 2; i++) {
                int idx = tid + i * 256;
                int r = idx >> 4, c = (idx & 15) * 8;
                cp16(sbase + (uint32_t)(15360 + ps * 4352 + r * 136 + c) * 2,
                     W + (size_t)(k0 + r) * Nc + tn + c);
            }
            cp_commit();
        }

        const half* As = hs + s * 5120;
        const half* Bs = hs + 15360 + s * 4352;
        #pragma unroll
        for (int ks = 0; ks < 2; ks++) {
            wmma::fragment<wmma::matrix_a, 16, 16, 16, half, wmma::row_major> af[2];
            wmma::load_matrix_sync(af[0], As + (wm * 32)      * 40 + ks * 16, 40);
            wmma::load_matrix_sync(af[1], As + (wm * 32 + 16) * 40 + ks * 16, 40);
            #pragma unroll
            for (int nn = 0; nn < 4; nn++) {
                wmma::fragment<wmma::matrix_b, 16, 16, 16, half, wmma::row_major> bf;
                wmma::load_matrix_sync(bf, Bs + (ks * 16) * 136 + wn * 64 + nn * 16, 136);
                wmma::mma_sync(acc[0][nn], af[0], bf, acc[0][nn]);
                wmma::mma_sync(acc[1][nn], af[1], bf, acc[1][nn]);
            }
        }
        s = (s == 2) ? 0 : s + 1;
    }
    __syncthreads();

    float* stg = fst + warp * 16 * 68;
    const int gcolb = tn + wn * 64;
    #pragma unroll
    for (int mm = 0; mm < 2; mm++) {
        #pragma unroll
        for (int nn = 0; nn < 4; nn++)
            wmma::store_matrix_sync(stg + nn * 16, acc[mm][nn], 68, wmma::mem_row_major);
        __syncwarp();
        const int growb = tm + wm * 32 + mm * 16;
        #pragma unroll
        for (int it = 0; it < 8; it++) {
            int e = it * 32 + lane;
            int rr = e >> 4;
            int cc = (e & 15) * 4;
            int col = gcolb + cc;
            float4 v = *(float4*)(stg + rr * 68 + cc);
            float4 bb4 = *(const float4*)(bias + col);
            v.x += bb4.x; v.y += bb4.y; v.z += bb4.z; v.w += bb4.w;
            storeC4h(C + (size_t)(growb + rr) * Nc + col, v);
        }
        __syncwarp();
    }
}

__global__ void __launch_bounds__(256, 2)
gemm_qkv(const half* __restrict__ A, const half* __restrict__ Wh,
         long wStride,
         const float* __restrict__ b0, const float* __restrict__ b1,
         const float* __restrict__ b2,
         half* __restrict__ C0, half* __restrict__ C1, half* __restrict__ C2,
         int Nc, int K) {
    extern __shared__ __align__(16) half dynsm[];
    const half* W = Wh + (size_t)blockIdx.z * wStride;
    const float* bb = (blockIdx.z == 0) ? b0 : (blockIdx.z == 1) ? b1 : b2;
    half* C = (blockIdx.z == 0) ? C0 : (blockIdx.z == 1) ? C1 : C2;
    gemm_body2(A, W, bb, C, Nc, K, dynsm);
}

// ---------------------------------------------------------------------------
// Mask-compacted FP16 flash attention, 2 heads per block.
// Dynamic smem layout (bytes):
//   Qs half [64][72]  @ 0      (9216 B)
//   Ks half [64][72]  @ 9216
//   Vs half [64][72]  @ 18432
//   Ph half [4][16][72] @ 27648 (9216 B)
//   Ps float [4][16][68] @ 36864 (17408 B)    total 54272 B
// ---------------------------------------------------------------------------
#define AT2_SMEM 54272
#define ALH 72
#define ALP 68

__global__ void __launch_bounds__(128)
attn_tc(const __half* __restrict__ q,
        const __half* __restrict__ k,
        const __half* __restrict__ v,
        const int*    __restrict__ idxs,
        const int*    __restrict__ cnts,
        __half* __restrict__ att) {
    extern __shared__ __align__(16) char asm_[];
    half*  Qs = (half*)asm_;                    // [64][72]
    half*  Ks = (half*)(asm_ + 9216);
    half*  Vs = (half*)(asm_ + 18432);
    half*  Ph = (half*)(asm_ + 27648);          // [4][16][72]
    float* Ps = (float*)(asm_ + 36864);         // [4][16][68]

    const int b = blockIdx.z;
    const int hp = blockIdx.y;                  // head pair: heads 2hp, 2hp+1
    const int tid = threadIdx.x;
    const int warp = tid >> 5;
    const int lane = tid & 31;
    const int qrow0 = blockIdx.x * 64;
    const int cbase = hp * 64;                  // column offset in D
    const float sc2 = 0.17677669529663687f * 1.4426950408889634f;

    const int count = cnts[b];
    const int nTiles = (count + 63) >> 6;

    // load Q (64 rows x 64 halves): thread r=tid>>1, c=(tid&1)*32
    {
        int r = tid >> 1, c = (tid & 1) * 32;
        const __half* src = q + ((size_t)(b * Nn + qrow0 + r)) * Dn + cbase + c;
        half* dst = Qs + r * ALH + c;
        *(uint4*)(dst)      = *(const uint4*)(src);
        *(uint4*)(dst + 8)  = *(const uint4*)(src + 8);
        *(uint4*)(dst + 16) = *(const uint4*)(src + 16);
        *(uint4*)(dst + 24) = *(const uint4*)(src + 24);
    }

    wmma::fragment<wmma::accumulator, 16, 16, 16, float> ao[2][2];
    #pragma unroll
    for (int hh = 0; hh < 2; hh++) {
        wmma::fill_fragment(ao[hh][0], 0.f);
        wmma::fill_fragment(ao[hh][1], 0.f);
    }

    float l_tot[2] = {0.f, 0.f};
    const int myrow = lane >> 1;
    const int colh = (lane & 1) * 32;

    for (int kt = 0; kt < nTiles; kt++) {
        __syncthreads();
        {
            int r = tid >> 1, c = (tid & 1) * 32;
            int g = kt * 64 + r;
            int col = (g < count) ? idxs[b * Nn + g] : 0;
            size_t off = ((size_t)(b * Nn + col)) * Dn + cbase + c;
            half* kd = Ks + r * ALH + c;
            half* vd = Vs + r * ALH + c;
            *(uint4*)(kd)      = *(const uint4*)(k + off);
            *(uint4*)(kd + 8)  = *(const uint4*)(k + off + 8);
            *(uint4*)(kd + 16) = *(const uint4*)(k + off + 16);
            *(uint4*)(kd + 24) = *(const uint4*)(k + off + 24);
            *(uint4*)(vd)      = *(const uint4*)(v + off);
            *(uint4*)(vd + 8)  = *(const uint4*)(v + off + 8);
            *(uint4*)(vd + 16) = *(const uint4*)(v + off + 16);
            *(uint4*)(vd + 24) = *(const uint4*)(v + off + 24);
        }
        __syncthreads();

        #pragma unroll
        for (int hh = 0; hh < 2; hh++) {
            const int hc = hh * 32;
            // S = Q @ K^T for this head
            wmma::fragment<wmma::accumulator, 16, 16, 16, float> sf[4];
            #pragma unroll
            for (int n = 0; n < 4; n++) wmma::fill_fragment(sf[n], 0.f);
            #pragma unroll
            for (int ks = 0; ks < 2; ks++) {
                wmma::fragment<wmma::matrix_a, 16, 16, 16, half, wmma::row_major> af;
                wmma::load_matrix_sync(af, Qs + (warp * 16) * ALH + hc + ks * 16, ALH);
                #pragma unroll
                for (int n = 0; n < 4; n++) {
                    wmma::fragment<wmma::matrix_b, 16, 16, 16, half, wmma::col_major> bf;
                    wmma::load_matrix_sync(bf, Ks + (n * 16) * ALH + hc + ks * 16, ALH);
                    wmma::mma_sync(sf[n], af, bf, sf[n]);
                }
            }
            float* PsW = Ps + warp * 16 * ALP;
            #pragma unroll
            for (int n = 0; n < 4; n++)
                wmma::store_matrix_sync(PsW + n * 16, sf[n], ALP, wmma::mem_row_major);
            __syncwarp();

            // p = 2^(s*sc2); row sums
            float lp = 0.f;
            const float* srow = PsW + myrow * ALP + colh;
            half* prow = Ph + (warp * 16 + myrow) * ALH + colh;
            const int jbase = kt * 64 + colh;
            const int nvalid = count - jbase;
            #pragma unroll
            for (int j = 0; j < 32; j += 2) {
                float a0 = (j     < nvalid) ? srow[j]     * sc2 : -1e4f;
                float a1 = (j + 1 < nvalid) ? srow[j + 1] * sc2 : -1e4f;
                half2 p2 = h2exp2(__floats2half2_rn(a0, a1));
                *(half2*)(prow + j) = p2;
                float2 pf = __half22float2(p2);
                lp += pf.x + pf.y;
            }
            lp += __shfl_xor_sync(0xffffffffu, lp, 1);
            l_tot[hh] += lp;
            __syncwarp();

            // O += P @ V (head's 32 V-cols)
            #pragma unroll
            for (int ks = 0; ks < 4; ks++) {
                wmma::fragment<wmma::matrix_a, 16, 16, 16, half, wmma::row_major> af;
                wmma::load_matrix_sync(af, Ph + (warp * 16) * ALH + ks * 16, ALH);
                #pragma unroll
                for (int n = 0; n < 2; n++) {
                    wmma::fragment<wmma::matrix_b, 16, 16, 16, half, wmma::row_major> bf;
                    wmma::load_matrix_sync(bf, Vs + (ks * 16) * ALH + hc + n * 16, ALH);
                    wmma::mma_sync(ao[hh][n], af, bf, ao[hh][n]);
                }
            }
            __syncwarp();
        }
    }

    // epilogue per head
    #pragma unroll
    for (int hh = 0; hh < 2; hh++) {
        float* Os = Ps + warp * 16 * ALP;
        wmma::store_matrix_sync(Os,      ao[hh][0], ALP, wmma::mem_row_major);
        wmma::store_matrix_sync(Os + 16, ao[hh][1], ALP, wmma::mem_row_major);
        __syncwarp();

        const float inv = 0.3f / l_tot[hh];
        const int ch = (lane & 1) * 16;
        __half* orow = att + ((size_t)(b * Nn + qrow0 + warp * 16 + myrow)) * Dn
                       + cbase + hh * 32 + ch;
        float* sro = Os + myrow * ALP + ch;
        #pragma unroll
        for (int c = 0; c < 8; c++) {
            half2 o2 = *(half2*)(orow + c * 2);
            float2 of = __half22float2(o2);
            of.x += sro[c * 2]     * inv;
            of.y += sro[c * 2 + 1] * inv;
            *(half2*)(orow + c * 2) = __floats2half2_rn(of.x, of.y);
        }
        __syncwarp();
    }
}

// ---------------------------------------------------------------------------
// Launch
// ---------------------------------------------------------------------------
extern "C" void kernel_launch(void* const* d_in, const int* in_sizes, int n_in,
                              void* d_out, int out_size) {
    const float* x_in  = (const float*)d_in[0];
    const int*   mask  = (const int*)  d_in[1];
    const float* adj   = (const float*)d_in[2];
    const float* dist  = (const float*)d_in[3];
    const float* Wq    = (const float*)d_in[5];
    const float* bq    = (const float*)d_in[6];
    const float* Wk    = (const float*)d_in[7];
    const float* bk    = (const float*)d_in[8];
    const float* Wv    = (const float*)d_in[9];
    const float* bv    = (const float*)d_in[10];
    const float* Wo    = (const float*)d_in[11];
    const float* bo    = (const float*)d_in[12];
    const float* Wf1   = (const float*)d_in[13];
    const float* bf1   = (const float*)d_in[14];
    const float* Wf2   = (const float*)d_in[15];
    const float* bf2   = (const float*)d_in[16];
    const float* ln1a  = (const float*)d_in[17];
    const float* ln1b  = (const float*)d_in[18];
    const float* ln2a  = (const float*)d_in[19];
    const float* ln2b  = (const float*)d_in[20];
    const float* lnfa  = (const float*)d_in[21];
    const float* lnfb  = (const float*)d_in[22];

    float *px;
    __half *pbaseh, *phh, *pqh, *pkh, *pvh, *pt1, *pph, *pwh;
    int *pidx, *pcnt;
    cudaGetSymbolAddress((void**)&px,     g_x);
    cudaGetSymbolAddress((void**)&pbaseh, g_baseh);
    cudaGetSymbolAddress((void**)&phh,    g_hh);
    cudaGetSymbolAddress((void**)&pqh,    g_qh);
    cudaGetSymbolAddress((void**)&pkh,    g_kh);
    cudaGetSymbolAddress((void**)&pvh,    g_vh);
    cudaGetSymbolAddress((void**)&pt1,    g_t1);
    cudaGetSymbolAddress((void**)&pph,    g_ph);
    cudaGetSymbolAddress((void**)&pwh,    g_wh);
    cudaGetSymbolAddress((void**)&pidx,   g_idx);
    cudaGetSymbolAddress((void**)&pcnt,   g_cnt);

    static bool attrDone = false;
    if (!attrDone) {
        cudaFuncSetAttribute(gemm_qkv, cudaFuncAttributeMaxDynamicSharedMemorySize, CA2_SMEM);
        cudaFuncSetAttribute(attn_tc,  cudaFuncAttributeMaxDynamicSharedMemorySize, AT2_SMEM);
        attrDone = true;
    }

    cudaMemcpyAsync(px, x_in, sizeof(float) * BND, cudaMemcpyDeviceToDevice, 0);

    cvt_w<<<(6 * WSZ) / 1024, 256>>>(Wq, Wk, Wv, Wo, Wf1, Wf2, pwh);
    base_kernel<<<Bn * Nn, 256>>>(dist, adj, mask, pbaseh);
    mask_idx_kernel<<<Bn, 512>>>(mask, pidx, pcnt);

    const dim3 gProj(Dn / 128, (Bn * Nn) / 64, 1);    // 256 blocks (64x128 tile)
    const dim3 gQKV (Dn / 128, (Bn * Nn) / 128, 3);   // 384 blocks (128x128 tile)
    const dim3 gBaseV(Dn / 128, Nn / 64, Bn);         // 256 blocks
    const dim3 gAttn(Nn / 64, Hn / 2, Bn);            // (8,4,16) = 512 blocks
    const dim3 gLN(Bn * Nn / 8, 1, 1);

    for (int i = 0; i < Ln; i++) {
        const size_t wOff = (size_t)i * Dn * Dn;
        const size_t vOff = (size_t)i * Dn;

        ln_h<<<gLN, 256>>>(px, ln1a + vOff, ln1b + vOff, phh);

        gemm_qkv<<<gQKV, 256, CA2_SMEM>>>(phh, pwh + wOff, (long)WSZ,
                                          bq + vOff, bk + vOff, bv + vOff,
                                          pqh, pkh, pvh, Dn, Dn);

        // att = base @ V  (half, K=512, 64x128 tile)
        gemm_hhz<<<gBaseV, 256>>>(pbaseh, pvh, pph, Dn, Nn,
                                  (long)Nn * Nn, (long)Nn * Dn, (long)Nn * Dn);

        // att += 0.3 * softmax @ V  (mask-compacted, 2 heads/block)
        attn_tc<<<gAttn, 128, AT2_SMEM>>>(pqh, pkh, pvh, pidx, pcnt, pph);

        // x = x + att @ Wo + bo
        gemm_hf<<<gProj, 256>>>(pph, pwh + 3 * WSZ + wOff, bo + vOff, px, px,
                                Dn, Dn, 0);

        // FFN
        ln_h<<<gLN, 256>>>(px, ln2a + vOff, ln2b + vOff, phh);
        gemm_hh<<<gProj, 256>>>(phh, pwh + 4 * WSZ + wOff, bf1 + vOff, pt1,
                                Dn, Dn, 1);
        gemm_hf<<<gProj, 256>>>(pt1, pwh + 5 * WSZ + wOff, bf2 + vOff, px, px,
                                Dn, Dn, 1);
    }

    ln_f<<<gLN, 256>>>(px, lnfa, lnfb, (float*)d_out);
}

// round 16
// speedup vs baseline: 1.0522x; 1.0522x over previous
#include <cuda_runtime.h>
#include <cuda_fp16.h>
#include <math.h>
#include <mma.h>
#include <stdint.h>

using namespace nvcuda;

// Problem constants
#define Bn 16
#define Nn 512
#define Dn 256
#define Hn 8
#define Ln 4
#define DKn 32

#define BND (Bn*Nn*Dn)   // 2,097,152
#define BNN (Bn*Nn*Nn)   // 4,194,304
#define WSZ (Ln*Dn*Dn)   // 262,144 per weight set

static __device__ float  g_x[BND];
static __device__ __half g_baseh[BNN];
static __device__ __half g_hh[BND];
static __device__ __half g_qh[BND];
static __device__ __half g_kh[BND];
static __device__ __half g_vh[BND];
static __device__ __half g_t1[BND];
static __device__ __half g_ph[BND];      // attention output (half)
static __device__ __half g_wh[6 * WSZ];
static __device__ int    g_idx[Bn * Nn];
static __device__ int    g_cnt[Bn];

// ---------------------------------------------------------------------------
// helpers
// ---------------------------------------------------------------------------
__device__ __forceinline__ uint4 pack_h8(float4 a, float4 b) {
    half2 h0 = __floats2half2_rn(a.x, a.y);
    half2 h1 = __floats2half2_rn(a.z, a.w);
    half2 h2 = __floats2half2_rn(b.x, b.y);
    half2 h3 = __floats2half2_rn(b.z, b.w);
    uint4 r;
    r.x = *(unsigned*)&h0; r.y = *(unsigned*)&h1;
    r.z = *(unsigned*)&h2; r.w = *(unsigned*)&h3;
    return r;
}

__device__ __forceinline__ void storeC4h(half* p, float4 v) {
    half2 a = __floats2half2_rn(v.x, v.y);
    half2 b = __floats2half2_rn(v.z, v.w);
    uint2 u; u.x = *(unsigned*)&a; u.y = *(unsigned*)&b;
    *(uint2*)p = u;
}

// cp.async primitives
__device__ __forceinline__ void cp16(uint32_t s, const void* g) {
    asm volatile("cp.async.cg.shared.global [%0], [%1], 16;" :: "r"(s), "l"(g));
}
__device__ __forceinline__ void cp_commit() {
    asm volatile("cp.async.commit_group;" ::: "memory");
}
__device__ __forceinline__ void cp_wait1() {
    asm volatile("cp.async.wait_group 1;" ::: "memory");
}
__device__ __forceinline__ void cp_wait0() {
    asm volatile("cp.async.wait_group 0;" ::: "memory");
}

// ---------------------------------------------------------------------------
// weight conversion fp32 -> fp16
// ---------------------------------------------------------------------------
__global__ void cvt_w(const float* __restrict__ Wq, const float* __restrict__ Wk,
                      const float* __restrict__ Wv, const float* __restrict__ Wo,
                      const float* __restrict__ Wf1, const float* __restrict__ Wf2,
                      __half* __restrict__ out) {
    const int idx = (blockIdx.x * 256 + threadIdx.x) * 4;
    const int w = idx / WSZ;
    const int r = idx - w * WSZ;
    const float* srcs[6] = {Wq, Wk, Wv, Wo, Wf1, Wf2};
    float4 v = *(const float4*)(srcs[w] + r);
    half2 a = __floats2half2_rn(v.x, v.y);
    half2 b = __floats2half2_rn(v.z, v.w);
    uint2 u; u.x = *(unsigned*)&a; u.y = *(unsigned*)&b;
    *(uint2*)(out + idx) = u;
}

// ---------------------------------------------------------------------------
// mask compaction
// ---------------------------------------------------------------------------
__global__ void mask_idx_kernel(const int* __restrict__ mask,
                                int* __restrict__ idx, int* __restrict__ cnt) {
    __shared__ int sc[512];
    const int b = blockIdx.x, t = threadIdx.x;
    const int m = (mask[b * Nn + t] != 0) ? 1 : 0;
    sc[t] = m;
    __syncthreads();
    for (int o = 1; o < 512; o <<= 1) {
        int v = (t >= o) ? sc[t - o] : 0;
        __syncthreads();
        sc[t] += v;
        __syncthreads();
    }
    if (m) idx[b * Nn + sc[t] - 1] = t;
    if (t == 511) cnt[b] = sc[511];
}

// ---------------------------------------------------------------------------
// block reductions (256 threads)
// ---------------------------------------------------------------------------
__device__ __forceinline__ float blockSum256(float v) {
    __shared__ float sm[8];
    __syncthreads();
    #pragma unroll
    for (int o = 16; o; o >>= 1) v += __shfl_xor_sync(0xffffffffu, v, o);
    if ((threadIdx.x & 31) == 0) sm[threadIdx.x >> 5] = v;
    __syncthreads();
    float t = 0.f;
    #pragma unroll
    for (int i = 0; i < 8; i++) t += sm[i];
    return t;
}

__device__ __forceinline__ float blockMax256(float v) {
    __shared__ float sm[8];
    __syncthreads();
    #pragma unroll
    for (int o = 16; o; o >>= 1) v = fmaxf(v, __shfl_xor_sync(0xffffffffu, v, o));
    if ((threadIdx.x & 31) == 0) sm[threadIdx.x >> 5] = v;
    __syncthreads();
    float t = sm[0];
    #pragma unroll
    for (int i = 1; i < 8; i++) t = fmaxf(t, sm[i]);
    return t;
}

// ---------------------------------------------------------------------------
// base (half output)
// ---------------------------------------------------------------------------
__global__ void base_kernel(const float* __restrict__ dist,
                            const float* __restrict__ adj,
                            const int*   __restrict__ mask,
                            __half* __restrict__ base) {
    const int bi = blockIdx.x;
    const int b  = bi >> 9;
    const float* dr = dist + (size_t)bi * Nn;
    const float* ar = adj  + (size_t)bi * Nn;
    __half*      br = base + (size_t)bi * Nn;
    const int t = threadIdx.x;

    const int m0 = mask[b * Nn + t];
    const int m1 = mask[b * Nn + t + 256];
    float v0 = m0 ? -dr[t]       : -INFINITY;
    float v1 = m1 ? -dr[t + 256] : -INFINITY;

    float mx = blockMax256(fmaxf(v0, v1));
    float e0 = __expf(v0 - mx);
    float e1 = __expf(v1 - mx);
    float ssum = blockSum256(e0 + e1);

    float a0 = ar[t], a1 = ar[t + 256];
    float asum = blockSum256(a0 + a1);

    float cs = 0.3f / ssum;
    float ca = 0.4f / (asum + 1e-6f);
    br[t]       = __float2half_rn(e0 * cs + a0 * ca);
    br[t + 256] = __float2half_rn(e1 * cs + a1 * ca);
}

// ---------------------------------------------------------------------------
// LayerNorm (ddof=1), warp per row
// ---------------------------------------------------------------------------
__device__ __forceinline__ void ln_core(const float* __restrict__ xr,
                                        const float* __restrict__ a,
                                        const float* __restrict__ bb,
                                        int c, float4& o0, float4& o1) {
    float4 v0 = *(const float4*)(xr + c);
    float4 v1 = *(const float4*)(xr + c + 4);
    float s = v0.x+v0.y+v0.z+v0.w + v1.x+v1.y+v1.z+v1.w;
    #pragma unroll
    for (int o = 16; o; o >>= 1) s += __shfl_xor_sync(0xffffffffu, s, o);
    float mean = s * (1.f / Dn);

    float c0[8] = {v0.x-mean, v0.y-mean, v0.z-mean, v0.w-mean,
                   v1.x-mean, v1.y-mean, v1.z-mean, v1.w-mean};
    float sq = 0.f;
    #pragma unroll
    for (int i = 0; i < 8; i++) sq += c0[i]*c0[i];
    #pragma unroll
    for (int o = 16; o; o >>= 1) sq += __shfl_xor_sync(0xffffffffu, sq, o);
    float inv = 1.f / (sqrtf(sq * (1.f / (Dn - 1))) + 1e-6f);

    float4 a0 = *(const float4*)(a + c);
    float4 a1 = *(const float4*)(a + c + 4);
    float4 b0 = *(const float4*)(bb + c);
    float4 b1 = *(const float4*)(bb + c + 4);
    o0.x = a0.x*c0[0]*inv + b0.x;  o0.y = a0.y*c0[1]*inv + b0.y;
    o0.z = a0.z*c0[2]*inv + b0.z;  o0.w = a0.w*c0[3]*inv + b0.w;
    o1.x = a1.x*c0[4]*inv + b1.x;  o1.y = a1.y*c0[5]*inv + b1.y;
    o1.z = a1.z*c0[6]*inv + b1.z;  o1.w = a1.w*c0[7]*inv + b1.w;
}

__global__ void ln_f(const float* __restrict__ x, const float* __restrict__ a,
                     const float* __restrict__ bb, float* __restrict__ out) {
    const size_t row = (size_t)blockIdx.x * 8 + (threadIdx.x >> 5);
    const int c = (threadIdx.x & 31) * 8;
    float4 o0, o1;
    ln_core(x + row * Dn, a, bb, c, o0, o1);
    *(float4*)(out + row * Dn + c)     = o0;
    *(float4*)(out + row * Dn + c + 4) = o1;
}

__global__ void ln_h(const float* __restrict__ x, const float* __restrict__ a,
                     const float* __restrict__ bb, __half* __restrict__ out) {
    const size_t row = (size_t)blockIdx.x * 8 + (threadIdx.x >> 5);
    const int c = (threadIdx.x & 31) * 8;
    float4 o0, o1;
    ln_core(x + row * Dn, a, bb, c, o0, o1);
    *(uint4*)(out + row * Dn + c) = pack_h8(o0, o1);
}

// ---------------------------------------------------------------------------
// Shared epilogue for 64x128 body
// ---------------------------------------------------------------------------
#define LDS_ 36

template<int CHALF>
__device__ __forceinline__ void gemm_epilogue(
    wmma::fragment<wmma::accumulator, 16, 16, 16, float> acc[2][2],
    float* fst, const float* bias, const float* res, void* Cv,
    int Nc, int act, int tm, int tn, int warp, int lane, int wm, int wn) {

    float* stg = fst + warp * 32 * LDS_;
    #pragma unroll
    for (int mm = 0; mm < 2; mm++)
        #pragma unroll
        for (int nn = 0; nn < 2; nn++)
            wmma::store_matrix_sync(stg + mm * 16 * LDS_ + nn * 16,
                                    acc[mm][nn], LDS_, wmma::mem_row_major);
    __syncwarp();

    const int growb = tm + wm * 32;
    const int gcolb = tn + wn * 32;
    #pragma unroll
    for (int it = 0; it < 8; it++) {
        int idx = it * 32 + lane;
        int rr = idx >> 3;
        int cc = (idx & 7) * 4;
        int col = gcolb + cc;
        float4 v = *(float4*)(stg + rr * LDS_ + cc);
        if (bias) {
            float4 bb4 = *(const float4*)(bias + col);
            v.x += bb4.x; v.y += bb4.y; v.z += bb4.z; v.w += bb4.w;
        }
        if (act) {
            v.x = v.x > 0.f ? v.x : 0.1f * v.x;
            v.y = v.y > 0.f ? v.y : 0.1f * v.y;
            v.z = v.z > 0.f ? v.z : 0.1f * v.z;
            v.w = v.w > 0.f ? v.w : 0.1f * v.w;
        }
        size_t row = (size_t)(growb + rr);
        if (CHALF) {
            storeC4h((half*)Cv + row * Nc + col, v);
        } else {
            float* Cf = (float*)Cv;
            if (res) {
                float4 r4 = *(const float4*)(res + row * Nc + col);
                v.x += r4.x; v.y += r4.y; v.z += r4.z; v.w += r4.w;
            }
            *(float4*)(Cf + row * Nc + col) = v;
        }
    }
}

// ---------------------------------------------------------------------------
// cp.async 3-stage GEMM, 64x128 tile (Wo/f1/f2/baseV: 256-block launches)
// ---------------------------------------------------------------------------
#define CA_SMEM_BYTES 41472

template<int CHALF>
__device__ __forceinline__ void gemm_body_ca(
    const half* __restrict__ A, const half* __restrict__ W,
    const float* __restrict__ bias, const float* __restrict__ res,
    void* __restrict__ Cv, int Nc, int K, int act, char* smemc) {

    half*  hs  = (half*)smemc;
    float* fst = (float*)smemc;

    const int tm = blockIdx.y * 64;
    const int tn = blockIdx.x * 128;
    const int tid = threadIdx.x;
    const int warp = tid >> 5;
    const int lane = tid & 31;
    const int wm = warp >> 2;
    const int wn = warp & 3;

    const int arow = tid >> 2;
    const int acol = (tid & 3) * 8;
    const uint32_t sbase = (uint32_t)__cvta_generic_to_shared(hs);

    const half* gA = A + (size_t)(tm + arow) * K + acol;

    wmma::fragment<wmma::accumulator, 16, 16, 16, float> acc[2][2];
    #pragma unroll
    for (int mm = 0; mm < 2; mm++)
        #pragma unroll
        for (int nn = 0; nn < 2; nn++)
            wmma::fill_fragment(acc[mm][nn], 0.f);

    const int nIter = K >> 5;

    #pragma unroll
    for (int p = 0; p < 2; p++) {
        int k0 = p * 32;
        cp16(sbase + (uint32_t)(p * 2560 + arow * 40 + acol) * 2, gA + k0);
        #pragma unroll
        for (int i = 0; i < 2; i++) {
            int idx = tid + i * 256;
            int r = idx >> 4, c = (idx & 15) * 8;
            cp16(sbase + (uint32_t)(7680 + p * 4352 + r * 136 + c) * 2,
                 W + (size_t)(k0 + r) * Nc + tn + c);
        }
        cp_commit();
    }

    int s = 0;
    for (int it = 0; it < nIter; it++) {
        if (it + 1 < nIter) cp_wait1(); else cp_wait0();
        __syncthreads();

        if (it + 2 < nIter) {
            int ps = (it + 2) % 3;
            int k0 = (it + 2) * 32;
            cp16(sbase + (uint32_t)(ps * 2560 + arow * 40 + acol) * 2, gA + k0);
            #pragma unroll
            for (int i = 0; i < 2; i++) {
                int idx = tid + i * 256;
                int r = idx >> 4, c = (idx & 15) * 8;
                cp16(sbase + (uint32_t)(7680 + ps * 4352 + r * 136 + c) * 2,
                     W + (size_t)(k0 + r) * Nc + tn + c);
            }
            cp_commit();
        }

        const half* As = hs + s * 2560;
        const half* Bs = hs + 7680 + s * 4352;
        #pragma unroll
        for (int ks = 0; ks < 2; ks++) {
            wmma::fragment<wmma::matrix_a, 16, 16, 16, half, wmma::row_major> af[2];
            wmma::fragment<wmma::matrix_b, 16, 16, 16, half, wmma::row_major> bf[2];
            wmma::load_matrix_sync(af[0], As + (wm * 32)      * 40 + ks * 16, 40);
            wmma::load_matrix_sync(af[1], As + (wm * 32 + 16) * 40 + ks * 16, 40);
            wmma::load_matrix_sync(bf[0], Bs + (ks * 16) * 136 + wn * 32,      136);
            wmma::load_matrix_sync(bf[1], Bs + (ks * 16) * 136 + wn * 32 + 16, 136);
            wmma::mma_sync(acc[0][0], af[0], bf[0], acc[0][0]);
            wmma::mma_sync(acc[0][1], af[0], bf[1], acc[0][1]);
            wmma::mma_sync(acc[1][0], af[1], bf[0], acc[1][0]);
            wmma::mma_sync(acc[1][1], af[1], bf[1], acc[1][1]);
        }
        s = (s == 2) ? 0 : s + 1;
    }
    __syncthreads();

    gemm_epilogue<CHALF>(acc, fst, bias, res, Cv, Nc, act, tm, tn, warp, lane, wm, wn);
}

__global__ void __launch_bounds__(256, 2)
gemm_hh(const half* __restrict__ A, const half* __restrict__ W,
        const float* __restrict__ bias, half* __restrict__ C,
        int Nc, int K, int act) {
    __shared__ __align__(16) char smem[CA_SMEM_BYTES];
    gemm_body_ca<1>(A, W, bias, nullptr, C, Nc, K, act, smem);
}

__global__ void __launch_bounds__(256, 2)
gemm_hf(const half* __restrict__ A, const half* __restrict__ W,
        const float* __restrict__ bias, const float* __restrict__ res,
        float* __restrict__ C, int Nc, int K, int act) {
    __shared__ __align__(16) char smem[CA_SMEM_BYTES];
    gemm_body_ca<0>(A, W, bias, res, C, Nc, K, act, smem);
}

__global__ void __launch_bounds__(256, 2)
gemm_hhz(const half* __restrict__ A, const half* __restrict__ W,
         half* __restrict__ C, int Nc, int K,
         long sA, long sW, long sC) {
    __shared__ __align__(16) char smem[CA_SMEM_BYTES];
    gemm_body_ca<1>(A + (size_t)blockIdx.z * sA, W + (size_t)blockIdx.z * sW,
                    nullptr, nullptr, C + (size_t)blockIdx.z * sC, Nc, K, 0, smem);
}

// ---------------------------------------------------------------------------
// cp.async 3-stage GEMM, 128x128 tile (qkv only, 384 blocks)
// ---------------------------------------------------------------------------
#define CA2_SMEM 56832

__device__ __forceinline__ void gemm_body2(
    const half* __restrict__ A, const half* __restrict__ W,
    const float* __restrict__ bias, half* __restrict__ C,
    int Nc, int K, half* hs) {

    float* fst = (float*)hs;

    const int tm = blockIdx.y * 128;
    const int tn = blockIdx.x * 128;
    const int tid = threadIdx.x;
    const int warp = tid >> 5;
    const int lane = tid & 31;
    const int wm = warp >> 1;
    const int wn = warp & 1;

    const int ar0 = tid >> 2;
    const int ac0 = (tid & 3) * 8;
    const uint32_t sbase = (uint32_t)__cvta_generic_to_shared(hs);

    const half* gA0 = A + (size_t)(tm + ar0) * K + ac0;
    const half* gA1 = gA0 + (size_t)64 * K;

    wmma::fragment<wmma::accumulator, 16, 16, 16, float> acc[2][4];
    #pragma unroll
    for (int mm = 0; mm < 2; mm++)
        #pragma unroll
        for (int nn = 0; nn < 4; nn++)
            wmma::fill_fragment(acc[mm][nn], 0.f);

    const int nIter = K >> 5;

    #pragma unroll
    for (int p = 0; p < 2; p++) {
        int k0 = p * 32;
        cp16(sbase + (uint32_t)(p * 5120 + ar0 * 40 + ac0) * 2, gA0 + k0);
        cp16(sbase + (uint32_t)(p * 5120 + (ar0 + 64) * 40 + ac0) * 2, gA1 + k0);
        #pragma unroll
        for (int i = 0; i < 2; i++) {
            int idx = tid + i * 256;
            int r = idx >> 4, c = (idx & 15) * 8;
            cp16(sbase + (uint32_t)(15360 + p * 4352 + r * 136 + c) * 2,
                 W + (size_t)(k0 + r) * Nc + tn + c);
        }
        cp_commit();
    }

    int s = 0;
    for (int it = 0; it < nIter; it++) {
        if (it + 1 < nIter) cp_wait1(); else cp_wait0();
        __syncthreads();

        if (it + 2 < nIter) {
            int ps = (it + 2) % 3;
            int k0 = (it + 2) * 32;
            cp16(sbase + (uint32_t)(ps * 5120 + ar0 * 40 + ac0) * 2, gA0 + k0);
            cp16(sbase + (uint32_t)(ps * 5120 + (ar0 + 64) * 40 + ac0) * 2, gA1 + k0);
            #pragma unroll
            for (int i = 0; i < 2; i++) {
                int idx = tid + i * 256;
                int r = idx >> 4, c = (idx & 15) * 8;
                cp16(sbase + (uint32_t)(15360 + ps * 4352 + r * 136 + c) * 2,
                     W + (size_t)(k0 + r) * Nc + tn + c);
            }
            cp_commit();
        }

        const half* As = hs + s * 5120;
        const half* Bs = hs + 15360 + s * 4352;
        #pragma unroll
        for (int ks = 0; ks < 2; ks++) {
            wmma::fragment<wmma::matrix_a, 16, 16, 16, half, wmma::row_major> af[2];
            wmma::load_matrix_sync(af[0], As + (wm * 32)      * 40 + ks * 16, 40);
            wmma::load_matrix_sync(af[1], As + (wm * 32 + 16) * 40 + ks * 16, 40);
            #pragma unroll
            for (int nn = 0; nn < 4; nn++) {
                wmma::fragment<wmma::matrix_b, 16, 16, 16, half, wmma::row_major> bf;
                wmma::load_matrix_sync(bf, Bs + (ks * 16) * 136 + wn * 64 + nn * 16, 136);
                wmma::mma_sync(acc[0][nn], af[0], bf, acc[0][nn]);
                wmma::mma_sync(acc[1][nn], af[1], bf, acc[1][nn]);
            }
        }
        s = (s == 2) ? 0 : s + 1;
    }
    __syncthreads();

    float* stg = fst + warp * 16 * 68;
    const int gcolb = tn + wn * 64;
    #pragma unroll
    for (int mm = 0; mm < 2; mm++) {
        #pragma unroll
        for (int nn = 0; nn < 4; nn++)
            wmma::store_matrix_sync(stg + nn * 16, acc[mm][nn], 68, wmma::mem_row_major);
        __syncwarp();
        const int growb = tm + wm * 32 + mm * 16;
        #pragma unroll
        for (int it = 0; it < 8; it++) {
            int e = it * 32 + lane;
            int rr = e >> 4;
            int cc = (e & 15) * 4;
            int col = gcolb + cc;
            float4 v = *(float4*)(stg + rr * 68 + cc);
            float4 bb4 = *(const float4*)(bias + col);
            v.x += bb4.x; v.y += bb4.y; v.z += bb4.z; v.w += bb4.w;
            storeC4h(C + (size_t)(growb + rr) * Nc + col, v);
        }
        __syncwarp();
    }
}

__global__ void __launch_bounds__(256, 2)
gemm_qkv(const half* __restrict__ A, const half* __restrict__ Wh,
         long wStride,
         const float* __restrict__ b0, const float* __restrict__ b1,
         const float* __restrict__ b2,
         half* __restrict__ C0, half* __restrict__ C1, half* __restrict__ C2,
         int Nc, int K) {
    extern __shared__ __align__(16) half dynsm[];
    const half* W = Wh + (size_t)blockIdx.z * wStride;
    const float* bb = (blockIdx.z == 0) ? b0 : (blockIdx.z == 1) ? b1 : b2;
    half* C = (blockIdx.z == 0) ? C0 : (blockIdx.z == 1) ? C1 : C2;
    gemm_body2(A, W, bb, C, Nc, K, dynsm);
}

// ---------------------------------------------------------------------------
// Mask-compacted FP16 flash attention (R14 version: 1 head/block, static smem)
// ---------------------------------------------------------------------------
#define ALQH 40
#define ALP  68
#define ALPH 72

__global__ void __launch_bounds__(128)
attn_tc(const __half* __restrict__ q,
        const __half* __restrict__ k,
        const __half* __restrict__ v,
        const int*    __restrict__ idxs,
        const int*    __restrict__ cnts,
        __half* __restrict__ att) {
    __shared__ __align__(16) half  Qs[64][ALQH];
    __shared__ __align__(16) half  Ks[64][ALQH];
    __shared__ __align__(16) half  Vs[64][ALQH];
    __shared__ __align__(16) float Ps[4][16][ALP];
    __shared__ __align__(16) half  Ph[4][16][ALPH];

    const int b = blockIdx.z, h = blockIdx.y;
    const int tid = threadIdx.x;
    const int warp = tid >> 5;
    const int lane = tid & 31;
    const int qrow0 = blockIdx.x * 64;
    const float sc2 = 0.17677669529663687f * 1.4426950408889634f;

    const int count = cnts[b];
    const int nTiles = (count + 63) >> 6;

    {
        int r = tid >> 1, c = (tid & 1) * 16;
        const __half* src = q + ((size_t)(b * Nn + qrow0 + r)) * Dn + h * DKn + c;
        *(uint4*)&Qs[r][c]     = *(const uint4*)(src);
        *(uint4*)&Qs[r][c + 8] = *(const uint4*)(src + 8);
    }

    wmma::fragment<wmma::accumulator, 16, 16, 16, float> ao[2];
    wmma::fill_fragment(ao[0], 0.f);
    wmma::fill_fragment(ao[1], 0.f);

    float l_tot = 0.f;
    const int myrow = lane >> 1;
    const int colh = (lane & 1) * 32;

    for (int kt = 0; kt < nTiles; kt++) {
        __syncthreads();
        {
            int r = tid >> 1, c = (tid & 1) * 16;
            int g = kt * 64 + r;
            int col = (g < count) ? idxs[b * Nn + g] : 0;
            size_t off = ((size_t)(b * Nn + col)) * Dn + h * DKn + c;
            *(uint4*)&Ks[r][c]     = *(const uint4*)(k + off);
            *(uint4*)&Ks[r][c + 8] = *(const uint4*)(k + off + 8);
            *(uint4*)&Vs[r][c]     = *(const uint4*)(v + off);
            *(uint4*)&Vs[r][c + 8] = *(const uint4*)(v + off + 8);
        }
        __syncthreads();

        wmma::fragment<wmma::accumulator, 16, 16, 16, float> sf[4];
        #pragma unroll
        for (int n = 0; n < 4; n++) wmma::fill_fragment(sf[n], 0.f);
        #pragma unroll
        for (int ks = 0; ks < 2; ks++) {
            wmma::fragment<wmma::matrix_a, 16, 16, 16, half, wmma::row_major> af;
            wmma::load_matrix_sync(af, &Qs[warp * 16][ks * 16], ALQH);
            #pragma unroll
            for (int n = 0; n < 4; n++) {
                wmma::fragment<wmma::matrix_b, 16, 16, 16, half, wmma::col_major> bf;
                wmma::load_matrix_sync(bf, &Ks[n * 16][ks * 16], ALQH);
                wmma::mma_sync(sf[n], af, bf, sf[n]);
            }
        }
        #pragma unroll
        for (int n = 0; n < 4; n++)
            wmma::store_matrix_sync(&Ps[warp][0][n * 16], sf[n], ALP, wmma::mem_row_major);
        __syncwarp();

        float lp = 0.f;
        const float* srow = &Ps[warp][myrow][colh];
        half* prow = &Ph[warp][myrow][colh];
        const int jbase = kt * 64 + colh;
        const int nvalid = count - jbase;
        #pragma unroll
        for (int j = 0; j < 32; j += 2) {
            float a0 = (j     < nvalid) ? srow[j]     * sc2 : -1e4f;
            float a1 = (j + 1 < nvalid) ? srow[j + 1] * sc2 : -1e4f;
            half2 p2 = h2exp2(__floats2half2_rn(a0, a1));
            *(half2*)(prow + j) = p2;
            float2 pf = __half22float2(p2);
            lp += pf.x + pf.y;
        }
        lp += __shfl_xor_sync(0xffffffffu, lp, 1);
        l_tot += lp;
        __syncwarp();

        #pragma unroll
        for (int ks = 0; ks < 4; ks++) {
            wmma::fragment<wmma::matrix_a, 16, 16, 16, half, wmma::row_major> af;
            wmma::load_matrix_sync(af, &Ph[warp][0][ks * 16], ALPH);
            #pragma unroll
            for (int n = 0; n < 2; n++) {
                wmma::fragment<wmma::matrix_b, 16, 16, 16, half, wmma::row_major> bf;
                wmma::load_matrix_sync(bf, &Vs[ks * 16][n * 16], ALQH);
                wmma::mma_sync(ao[n], af, bf, ao[n]);
            }
        }
    }

    float* Os = &Ps[warp][0][0];
    wmma::store_matrix_sync(Os,      ao[0], ALP, wmma::mem_row_major);
    wmma::store_matrix_sync(Os + 16, ao[1], ALP, wmma::mem_row_major);
    __syncwarp();

    const float inv = 0.3f / l_tot;
    const int ch = (lane & 1) * 16;
    __half* orow = att + ((size_t)(b * Nn + qrow0 + warp * 16 + myrow)) * Dn + h * DKn + ch;
    float* sro = Os + myrow * ALP + ch;
    #pragma unroll
    for (int c = 0; c < 8; c++) {
        half2 o2 = *(half2*)(orow + c * 2);
        float2 of = __half22float2(o2);
        of.x += sro[c * 2]     * inv;
        of.y += sro[c * 2 + 1] * inv;
        *(half2*)(orow + c * 2) = __floats2half2_rn(of.x, of.y);
    }
}

// ---------------------------------------------------------------------------
// Launch
// ---------------------------------------------------------------------------
extern "C" void kernel_launch(void* const* d_in, const int* in_sizes, int n_in,
                              void* d_out, int out_size) {
    const float* x_in  = (const float*)d_in[0];
    const int*   mask  = (const int*)  d_in[1];
    const float* adj   = (const float*)d_in[2];
    const float* dist  = (const float*)d_in[3];
    const float* Wq    = (const float*)d_in[5];
    const float* bq    = (const float*)d_in[6];
    const float* Wk    = (const float*)d_in[7];
    const float* bk    = (const float*)d_in[8];
    const float* Wv    = (const float*)d_in[9];
    const float* bv    = (const float*)d_in[10];
    const float* Wo    = (const float*)d_in[11];
    const float* bo    = (const float*)d_in[12];
    const float* Wf1   = (const float*)d_in[13];
    const float* bf1   = (const float*)d_in[14];
    const float* Wf2   = (const float*)d_in[15];
    const float* bf2   = (const float*)d_in[16];
    const float* ln1a  = (const float*)d_in[17];
    const float* ln1b  = (const float*)d_in[18];
    const float* ln2a  = (const float*)d_in[19];
    const float* ln2b  = (const float*)d_in[20];
    const float* lnfa  = (const float*)d_in[21];
    const float* lnfb  = (const float*)d_in[22];

    float *px;
    __half *pbaseh, *phh, *pqh, *pkh, *pvh, *pt1, *pph, *pwh;
    int *pidx, *pcnt;
    cudaGetSymbolAddress((void**)&px,     g_x);
    cudaGetSymbolAddress((void**)&pbaseh, g_baseh);
    cudaGetSymbolAddress((void**)&phh,    g_hh);
    cudaGetSymbolAddress((void**)&pqh,    g_qh);
    cudaGetSymbolAddress((void**)&pkh,    g_kh);
    cudaGetSymbolAddress((void**)&pvh,    g_vh);
    cudaGetSymbolAddress((void**)&pt1,    g_t1);
    cudaGetSymbolAddress((void**)&pph,    g_ph);
    cudaGetSymbolAddress((void**)&pwh,    g_wh);
    cudaGetSymbolAddress((void**)&pidx,   g_idx);
    cudaGetSymbolAddress((void**)&pcnt,   g_cnt);

    static bool attrDone = false;
    if (!attrDone) {
        cudaFuncSetAttribute(gemm_qkv, cudaFuncAttributeMaxDynamicSharedMemorySize, CA2_SMEM);
        attrDone = true;
    }

    cudaMemcpyAsync(px, x_in, sizeof(float) * BND, cudaMemcpyDeviceToDevice, 0);

    cvt_w<<<(6 * WSZ) / 1024, 256>>>(Wq, Wk, Wv, Wo, Wf1, Wf2, pwh);
    base_kernel<<<Bn * Nn, 256>>>(dist, adj, mask, pbaseh);
    mask_idx_kernel<<<Bn, 512>>>(mask, pidx, pcnt);

    const dim3 gProj(Dn / 128, (Bn * Nn) / 64, 1);    // 256 blocks (64x128 tile)
    const dim3 gQKV (Dn / 128, (Bn * Nn) / 128, 3);   // 384 blocks (128x128 tile)
    const dim3 gBaseV(Dn / 128, Nn / 64, Bn);         // 256 blocks
    const dim3 gAttn(Nn / 64, Hn, Bn);                // 1024 blocks
    const dim3 gLN(Bn * Nn / 8, 1, 1);

    for (int i = 0; i < Ln; i++) {
        const size_t wOff = (size_t)i * Dn * Dn;
        const size_t vOff = (size_t)i * Dn;

        ln_h<<<gLN, 256>>>(px, ln1a + vOff, ln1b + vOff, phh);

        gemm_qkv<<<gQKV, 256, CA2_SMEM>>>(phh, pwh + wOff, (long)WSZ,
                                          bq + vOff, bk + vOff, bv + vOff,
                                          pqh, pkh, pvh, Dn, Dn);

        // att = base @ V  (half, K=512, 64x128 tile, 256 blocks)
        gemm_hhz<<<gBaseV, 256>>>(pbaseh, pvh, pph, Dn, Nn,
                                  (long)Nn * Nn, (long)Nn * Dn, (long)Nn * Dn);

        // att += 0.3 * softmax @ V  (mask-compacted, 1 head/block)
        attn_tc<<<gAttn, 128>>>(pqh, pkh, pvh, pidx, pcnt, pph);

        // x = x + att @ Wo + bo  (64x128 tile, 256 blocks)
        gemm_hf<<<gProj, 256>>>(pph, pwh + 3 * WSZ + wOff, bo + vOff, px, px,
                                Dn, Dn, 0);

        // FFN (64x128 tile, 256 blocks)
        ln_h<<<gLN, 256>>>(px, ln2a + vOff, ln2b + vOff, phh);
        gemm_hh<<<gProj, 256>>>(phh, pwh + 4 * WSZ + wOff, bf1 + vOff, pt1,
                                Dn, Dn, 1);
        gemm_hf<<<gProj, 256>>>(pt1, pwh + 5 * WSZ + wOff, bf2 + vOff, px, px,
                                Dn, Dn, 1);
    }

    ln_f<<<gLN, 256>>>(px, lnfa, lnfb, (float*)d_out);
}

// round 17
// speedup vs baseline: 1.1025x; 1.0478x over previous
#include <cuda_runtime.h>
#include <cuda_fp16.h>
#include <math.h>
#include <mma.h>
#include <stdint.h>

using namespace nvcuda;

// Problem constants
#define Bn 16
#define Nn 512
#define Dn 256
#define Hn 8
#define Ln 4
#define DKn 32

#define BND (Bn*Nn*Dn)   // 2,097,152
#define BNN (Bn*Nn*Nn)   // 4,194,304
#define WSZ (Ln*Dn*Dn)   // 262,144 per weight set

static __device__ float  g_x[BND];
static __device__ __half g_baseh[BNN];
static __device__ __half g_hh[BND];
static __device__ __half g_qh[BND];
static __device__ __half g_kh[BND];
static __device__ __half g_vh[BND];
static __device__ __half g_t1[BND];
static __device__ __half g_ph[BND];      // attention output (half)
static __device__ __half g_wh[6 * WSZ];
static __device__ int    g_idx[Bn * Nn];
static __device__ int    g_cnt[Bn];

// ---------------------------------------------------------------------------
// helpers
// ---------------------------------------------------------------------------
__device__ __forceinline__ uint4 pack_h8(float4 a, float4 b) {
    half2 h0 = __floats2half2_rn(a.x, a.y);
    half2 h1 = __floats2half2_rn(a.z, a.w);
    half2 h2 = __floats2half2_rn(b.x, b.y);
    half2 h3 = __floats2half2_rn(b.z, b.w);
    uint4 r;
    r.x = *(unsigned*)&h0; r.y = *(unsigned*)&h1;
    r.z = *(unsigned*)&h2; r.w = *(unsigned*)&h3;
    return r;
}

__device__ __forceinline__ void storeC4h(half* p, float4 v) {
    half2 a = __floats2half2_rn(v.x, v.y);
    half2 b = __floats2half2_rn(v.z, v.w);
    uint2 u; u.x = *(unsigned*)&a; u.y = *(unsigned*)&b;
    *(uint2*)p = u;
}

// cp.async primitives
__device__ __forceinline__ void cp16(uint32_t s, const void* g) {
    asm volatile("cp.async.cg.shared.global [%0], [%1], 16;" :: "r"(s), "l"(g));
}
__device__ __forceinline__ void cp_commit() {
    asm volatile("cp.async.commit_group;" ::: "memory");
}
__device__ __forceinline__ void cp_wait1() {
    asm volatile("cp.async.wait_group 1;" ::: "memory");
}
__device__ __forceinline__ void cp_wait0() {
    asm volatile("cp.async.wait_group 0;" ::: "memory");
}

// ---------------------------------------------------------------------------
// weight conversion fp32 -> fp16
// ---------------------------------------------------------------------------
__global__ void cvt_w(const float* __restrict__ Wq, const float* __restrict__ Wk,
                      const float* __restrict__ Wv, const float* __restrict__ Wo,
                      const float* __restrict__ Wf1, const float* __restrict__ Wf2,
                      __half* __restrict__ out) {
    const int idx = (blockIdx.x * 256 + threadIdx.x) * 4;
    const int w = idx / WSZ;
    const int r = idx - w * WSZ;
    const float* srcs[6] = {Wq, Wk, Wv, Wo, Wf1, Wf2};
    float4 v = *(const float4*)(srcs[w] + r);
    half2 a = __floats2half2_rn(v.x, v.y);
    half2 b = __floats2half2_rn(v.z, v.w);
    uint2 u; u.x = *(unsigned*)&a; u.y = *(unsigned*)&b;
    *(uint2*)(out + idx) = u;
}

// ---------------------------------------------------------------------------
// mask compaction
// ---------------------------------------------------------------------------
__global__ void mask_idx_kernel(const int* __restrict__ mask,
                                int* __restrict__ idx, int* __restrict__ cnt) {
    __shared__ int sc[512];
    const int b = blockIdx.x, t = threadIdx.x;
    const int m = (mask[b * Nn + t] != 0) ? 1 : 0;
    sc[t] = m;
    __syncthreads();
    for (int o = 1; o < 512; o <<= 1) {
        int v = (t >= o) ? sc[t - o] : 0;
        __syncthreads();
        sc[t] += v;
        __syncthreads();
    }
    if (m) idx[b * Nn + sc[t] - 1] = t;
    if (t == 511) cnt[b] = sc[511];
}

// ---------------------------------------------------------------------------
// block reductions (256 threads)
// ---------------------------------------------------------------------------
__device__ __forceinline__ float blockSum256(float v) {
    __shared__ float sm[8];
    __syncthreads();
    #pragma unroll
    for (int o = 16; o; o >>= 1) v += __shfl_xor_sync(0xffffffffu, v, o);
    if ((threadIdx.x & 31) == 0) sm[threadIdx.x >> 5] = v;
    __syncthreads();
    float t = 0.f;
    #pragma unroll
    for (int i = 0; i < 8; i++) t += sm[i];
    return t;
}

__device__ __forceinline__ float blockMax256(float v) {
    __shared__ float sm[8];
    __syncthreads();
    #pragma unroll
    for (int o = 16; o; o >>= 1) v = fmaxf(v, __shfl_xor_sync(0xffffffffu, v, o));
    if ((threadIdx.x & 31) == 0) sm[threadIdx.x >> 5] = v;
    __syncthreads();
    float t = sm[0];
    #pragma unroll
    for (int i = 1; i < 8; i++) t = fmaxf(t, sm[i]);
    return t;
}

// ---------------------------------------------------------------------------
// base (half output)
// ---------------------------------------------------------------------------
__global__ void base_kernel(const float* __restrict__ dist,
                            const float* __restrict__ adj,
                            const int*   __restrict__ mask,
                            __half* __restrict__ base) {
    const int bi = blockIdx.x;
    const int b  = bi >> 9;
    const float* dr = dist + (size_t)bi * Nn;
    const float* ar = adj  + (size_t)bi * Nn;
    __half*      br = base + (size_t)bi * Nn;
    const int t = threadIdx.x;

    const int m0 = mask[b * Nn + t];
    const int m1 = mask[b * Nn + t + 256];
    float v0 = m0 ? -dr[t]       : -INFINITY;
    float v1 = m1 ? -dr[t + 256] : -INFINITY;

    float mx = blockMax256(fmaxf(v0, v1));
    float e0 = __expf(v0 - mx);
    float e1 = __expf(v1 - mx);
    float ssum = blockSum256(e0 + e1);

    float a0 = ar[t], a1 = ar[t + 256];
    float asum = blockSum256(a0 + a1);

    float cs = 0.3f / ssum;
    float ca = 0.4f / (asum + 1e-6f);
    br[t]       = __float2half_rn(e0 * cs + a0 * ca);
    br[t + 256] = __float2half_rn(e1 * cs + a1 * ca);
}

// ---------------------------------------------------------------------------
// LayerNorm (ddof=1), warp per row
// ---------------------------------------------------------------------------
__device__ __forceinline__ void ln_core(const float* __restrict__ xr,
                                        const float* __restrict__ a,
                                        const float* __restrict__ bb,
                                        int c, float4& o0, float4& o1) {
    float4 v0 = *(const float4*)(xr + c);
    float4 v1 = *(const float4*)(xr + c + 4);
    float s = v0.x+v0.y+v0.z+v0.w + v1.x+v1.y+v1.z+v1.w;
    #pragma unroll
    for (int o = 16; o; o >>= 1) s += __shfl_xor_sync(0xffffffffu, s, o);
    float mean = s * (1.f / Dn);

    float c0[8] = {v0.x-mean, v0.y-mean, v0.z-mean, v0.w-mean,
                   v1.x-mean, v1.y-mean, v1.z-mean, v1.w-mean};
    float sq = 0.f;
    #pragma unroll
    for (int i = 0; i < 8; i++) sq += c0[i]*c0[i];
    #pragma unroll
    for (int o = 16; o; o >>= 1) sq += __shfl_xor_sync(0xffffffffu, sq, o);
    float inv = 1.f / (sqrtf(sq * (1.f / (Dn - 1))) + 1e-6f);

    float4 a0 = *(const float4*)(a + c);
    float4 a1 = *(const float4*)(a + c + 4);
    float4 b0 = *(const float4*)(bb + c);
    float4 b1 = *(const float4*)(bb + c + 4);
    o0.x = a0.x*c0[0]*inv + b0.x;  o0.y = a0.y*c0[1]*inv + b0.y;
    o0.z = a0.z*c0[2]*inv + b0.z;  o0.w = a0.w*c0[3]*inv + b0.w;
    o1.x = a1.x*c0[4]*inv + b1.x;  o1.y = a1.y*c0[5]*inv + b1.y;
    o1.z = a1.z*c0[6]*inv + b1.z;  o1.w = a1.w*c0[7]*inv + b1.w;
}

__global__ void ln_f(const float* __restrict__ x, const float* __restrict__ a,
                     const float* __restrict__ bb, float* __restrict__ out) {
    const size_t row = (size_t)blockIdx.x * 8 + (threadIdx.x >> 5);
    const int c = (threadIdx.x & 31) * 8;
    float4 o0, o1;
    ln_core(x + row * Dn, a, bb, c, o0, o1);
    *(float4*)(out + row * Dn + c)     = o0;
    *(float4*)(out + row * Dn + c + 4) = o1;
}

__global__ void ln_h(const float* __restrict__ x, const float* __restrict__ a,
                     const float* __restrict__ bb, __half* __restrict__ out) {
    const size_t row = (size_t)blockIdx.x * 8 + (threadIdx.x >> 5);
    const int c = (threadIdx.x & 31) * 8;
    float4 o0, o1;
    ln_core(x + row * Dn, a, bb, c, o0, o1);
    *(uint4*)(out + row * Dn + c) = pack_h8(o0, o1);
}

// ---------------------------------------------------------------------------
// Shared epilogue for 64x128 body
// ---------------------------------------------------------------------------
#define LDS_ 36

template<int CHALF>
__device__ __forceinline__ void gemm_epilogue(
    wmma::fragment<wmma::accumulator, 16, 16, 16, float> acc[2][2],
    float* fst, const float* bias, const float* res, void* Cv,
    int Nc, int act, int tm, int tn, int warp, int lane, int wm, int wn) {

    float* stg = fst + warp * 32 * LDS_;
    #pragma unroll
    for (int mm = 0; mm < 2; mm++)
        #pragma unroll
        for (int nn = 0; nn < 2; nn++)
            wmma::store_matrix_sync(stg + mm * 16 * LDS_ + nn * 16,
                                    acc[mm][nn], LDS_, wmma::mem_row_major);
    __syncwarp();

    const int growb = tm + wm * 32;
    const int gcolb = tn + wn * 32;
    #pragma unroll
    for (int it = 0; it < 8; it++) {
        int idx = it * 32 + lane;
        int rr = idx >> 3;
        int cc = (idx & 7) * 4;
        int col = gcolb + cc;
        float4 v = *(float4*)(stg + rr * LDS_ + cc);
        if (bias) {
            float4 bb4 = *(const float4*)(bias + col);
            v.x += bb4.x; v.y += bb4.y; v.z += bb4.z; v.w += bb4.w;
        }
        if (act) {
            v.x = v.x > 0.f ? v.x : 0.1f * v.x;
            v.y = v.y > 0.f ? v.y : 0.1f * v.y;
            v.z = v.z > 0.f ? v.z : 0.1f * v.z;
            v.w = v.w > 0.f ? v.w : 0.1f * v.w;
        }
        size_t row = (size_t)(growb + rr);
        if (CHALF) {
            storeC4h((half*)Cv + row * Nc + col, v);
        } else {
            float* Cf = (float*)Cv;
            if (res) {
                float4 r4 = *(const float4*)(res + row * Nc + col);
                v.x += r4.x; v.y += r4.y; v.z += r4.z; v.w += r4.w;
            }
            *(float4*)(Cf + row * Nc + col) = v;
        }
    }
}

// ---------------------------------------------------------------------------
// cp.async 3-stage GEMM, 64x128 tile (Wo/f1/f2/baseV: 256-block launches)
// ---------------------------------------------------------------------------
#define CA_SMEM_BYTES 41472

template<int CHALF>
__device__ __forceinline__ void gemm_body_ca(
    const half* __restrict__ A, const half* __restrict__ W,
    const float* __restrict__ bias, const float* __restrict__ res,
    void* __restrict__ Cv, int Nc, int K, int act, char* smemc) {

    half*  hs  = (half*)smemc;
    float* fst = (float*)smemc;

    const int tm = blockIdx.y * 64;
    const int tn = blockIdx.x * 128;
    const int tid = threadIdx.x;
    const int warp = tid >> 5;
    const int lane = tid & 31;
    const int wm = warp >> 2;
    const int wn = warp & 3;

    const int arow = tid >> 2;
    const int acol = (tid & 3) * 8;
    const uint32_t sbase = (uint32_t)__cvta_generic_to_shared(hs);

    const half* gA = A + (size_t)(tm + arow) * K + acol;

    wmma::fragment<wmma::accumulator, 16, 16, 16, float> acc[2][2];
    #pragma unroll
    for (int mm = 0; mm < 2; mm++)
        #pragma unroll
        for (int nn = 0; nn < 2; nn++)
            wmma::fill_fragment(acc[mm][nn], 0.f);

    const int nIter = K >> 5;

    #pragma unroll
    for (int p = 0; p < 2; p++) {
        int k0 = p * 32;
        cp16(sbase + (uint32_t)(p * 2560 + arow * 40 + acol) * 2, gA + k0);
        #pragma unroll
        for (int i = 0; i < 2; i++) {
            int idx = tid + i * 256;
            int r = idx >> 4, c = (idx & 15) * 8;
            cp16(sbase + (uint32_t)(7680 + p * 4352 + r * 136 + c) * 2,
                 W + (size_t)(k0 + r) * Nc + tn + c);
        }
        cp_commit();
    }

    int s = 0;
    for (int it = 0; it < nIter; it++) {
        if (it + 1 < nIter) cp_wait1(); else cp_wait0();
        __syncthreads();

        if (it + 2 < nIter) {
            int ps = (it + 2) % 3;
            int k0 = (it + 2) * 32;
            cp16(sbase + (uint32_t)(ps * 2560 + arow * 40 + acol) * 2, gA + k0);
            #pragma unroll
            for (int i = 0; i < 2; i++) {
                int idx = tid + i * 256;
                int r = idx >> 4, c = (idx & 15) * 8;
                cp16(sbase + (uint32_t)(7680 + ps * 4352 + r * 136 + c) * 2,
                     W + (size_t)(k0 + r) * Nc + tn + c);
            }
            cp_commit();
        }

        const half* As = hs + s * 2560;
        const half* Bs = hs + 7680 + s * 4352;
        #pragma unroll
        for (int ks = 0; ks < 2; ks++) {
            wmma::fragment<wmma::matrix_a, 16, 16, 16, half, wmma::row_major> af[2];
            wmma::fragment<wmma::matrix_b, 16, 16, 16, half, wmma::row_major> bf[2];
            wmma::load_matrix_sync(af[0], As + (wm * 32)      * 40 + ks * 16, 40);
            wmma::load_matrix_sync(af[1], As + (wm * 32 + 16) * 40 + ks * 16, 40);
            wmma::load_matrix_sync(bf[0], Bs + (ks * 16) * 136 + wn * 32,      136);
            wmma::load_matrix_sync(bf[1], Bs + (ks * 16) * 136 + wn * 32 + 16, 136);
            wmma::mma_sync(acc[0][0], af[0], bf[0], acc[0][0]);
            wmma::mma_sync(acc[0][1], af[0], bf[1], acc[0][1]);
            wmma::mma_sync(acc[1][0], af[1], bf[0], acc[1][0]);
            wmma::mma_sync(acc[1][1], af[1], bf[1], acc[1][1]);
        }
        s = (s == 2) ? 0 : s + 1;
    }
    __syncthreads();

    gemm_epilogue<CHALF>(acc, fst, bias, res, Cv, Nc, act, tm, tn, warp, lane, wm, wn);
}

__global__ void __launch_bounds__(256, 2)
gemm_hh(const half* __restrict__ A, const half* __restrict__ W,
        const float* __restrict__ bias, half* __restrict__ C,
        int Nc, int K, int act) {
    __shared__ __align__(16) char smem[CA_SMEM_BYTES];
    gemm_body_ca<1>(A, W, bias, nullptr, C, Nc, K, act, smem);
}

__global__ void __launch_bounds__(256, 2)
gemm_hf(const half* __restrict__ A, const half* __restrict__ W,
        const float* __restrict__ bias, const float* __restrict__ res,
        float* __restrict__ C, int Nc, int K, int act) {
    __shared__ __align__(16) char smem[CA_SMEM_BYTES];
    gemm_body_ca<0>(A, W, bias, res, C, Nc, K, act, smem);
}

__global__ void __launch_bounds__(256, 2)
gemm_hhz(const half* __restrict__ A, const half* __restrict__ W,
         half* __restrict__ C, int Nc, int K,
         long sA, long sW, long sC) {
    __shared__ __align__(16) char smem[CA_SMEM_BYTES];
    gemm_body_ca<1>(A + (size_t)blockIdx.z * sA, W + (size_t)blockIdx.z * sW,
                    nullptr, nullptr, C + (size_t)blockIdx.z * sC, Nc, K, 0, smem);
}

// ---------------------------------------------------------------------------
// cp.async 3-stage GEMM, 128x128 tile (qkv only, 384 blocks)
// ---------------------------------------------------------------------------
#define CA2_SMEM 56832

__device__ __forceinline__ void gemm_body2(
    const half* __restrict__ A, const half* __restrict__ W,
    const float* __restrict__ bias, half* __restrict__ C,
    int Nc, int K, half* hs) {

    float* fst = (float*)hs;

    const int tm = blockIdx.y * 128;
    const int tn = blockIdx.x * 128;
    const int tid = threadIdx.x;
    const int warp = tid >> 5;
    const int lane = tid & 31;
    const int wm = warp >> 1;
    const int wn = warp & 1;

    const int ar0 = tid >> 2;
    const int ac0 = (tid & 3) * 8;
    const uint32_t sbase = (uint32_t)__cvta_generic_to_shared(hs);

    const half* gA0 = A + (size_t)(tm + ar0) * K + ac0;
    const half* gA1 = gA0 + (size_t)64 * K;

    wmma::fragment<wmma::accumulator, 16, 16, 16, float> acc[2][4];
    #pragma unroll
    for (int mm = 0; mm < 2; mm++)
        #pragma unroll
        for (int nn = 0; nn < 4; nn++)
            wmma::fill_fragment(acc[mm][nn], 0.f);

    const int nIter = K >> 5;

    #pragma unroll
    for (int p = 0; p < 2; p++) {
        int k0 = p * 32;
        cp16(sbase + (uint32_t)(p * 5120 + ar0 * 40 + ac0) * 2, gA0 + k0);
        cp16(sbase + (uint32_t)(p * 5120 + (ar0 + 64) * 40 + ac0) * 2, gA1 + k0);
        #pragma unroll
        for (int i = 0; i < 2; i++) {
            int idx = tid + i * 256;
            int r = idx >> 4, c = (idx & 15) * 8;
            cp16(sbase + (uint32_t)(15360 + p * 4352 + r * 136 + c) * 2,
                 W + (size_t)(k0 + r) * Nc + tn + c);
        }
        cp_commit();
    }

    int s = 0;
    for (int it = 0; it < nIter; it++) {
        if (it + 1 < nIter) cp_wait1(); else cp_wait0();
        __syncthreads();

        if (it + 2 < nIter) {
            int ps = (it + 2) % 3;
            int k0 = (it + 2) * 32;
            cp16(sbase + (uint32_t)(ps * 5120 + ar0 * 40 + ac0) * 2, gA0 + k0);
            cp16(sbase + (uint32_t)(ps * 5120 + (ar0 + 64) * 40 + ac0) * 2, gA1 + k0);
            #pragma unroll
            for (int i = 0; i < 2; i++) {
                int idx = tid + i * 256;
                int r = idx >> 4, c = (idx & 15) * 8;
                cp16(sbase + (uint32_t)(15360 + ps * 4352 + r * 136 + c) * 2,
                     W + (size_t)(k0 + r) * Nc + tn + c);
            }
            cp_commit();
        }

        const half* As = hs + s * 5120;
        const half* Bs = hs + 15360 + s * 4352;
        #pragma unroll
        for (int ks = 0; ks < 2; ks++) {
            wmma::fragment<wmma::matrix_a, 16, 16, 16, half, wmma::row_major> af[2];
            wmma::load_matrix_sync(af[0], As + (wm * 32)      * 40 + ks * 16, 40);
            wmma::load_matrix_sync(af[1], As + (wm * 32 + 16) * 40 + ks * 16, 40);
            #pragma unroll
            for (int nn = 0; nn < 4; nn++) {
                wmma::fragment<wmma::matrix_b, 16, 16, 16, half, wmma::row_major> bf;
                wmma::load_matrix_sync(bf, Bs + (ks * 16) * 136 + wn * 64 + nn * 16, 136);
                wmma::mma_sync(acc[0][nn], af[0], bf, acc[0][nn]);
                wmma::mma_sync(acc[1][nn], af[1], bf, acc[1][nn]);
            }
        }
        s = (s == 2) ? 0 : s + 1;
    }
    __syncthreads();

    float* stg = fst + warp * 16 * 68;
    const int gcolb = tn + wn * 64;
    #pragma unroll
    for (int mm = 0; mm < 2; mm++) {
        #pragma unroll
        for (int nn = 0; nn < 4; nn++)
            wmma::store_matrix_sync(stg + nn * 16, acc[mm][nn], 68, wmma::mem_row_major);
        __syncwarp();
        const int growb = tm + wm * 32 + mm * 16;
        #pragma unroll
        for (int it = 0; it < 8; it++) {
            int e = it * 32 + lane;
            int rr = e >> 4;
            int cc = (e & 15) * 4;
            int col = gcolb + cc;
            float4 v = *(float4*)(stg + rr * 68 + cc);
            float4 bb4 = *(const float4*)(bias + col);
            v.x += bb4.x; v.y += bb4.y; v.z += bb4.z; v.w += bb4.w;
            storeC4h(C + (size_t)(growb + rr) * Nc + col, v);
        }
        __syncwarp();
    }
}

__global__ void __launch_bounds__(256, 2)
gemm_qkv(const half* __restrict__ A, const half* __restrict__ Wh,
         long wStride,
         const float* __restrict__ b0, const float* __restrict__ b1,
         const float* __restrict__ b2,
         half* __restrict__ C0, half* __restrict__ C1, half* __restrict__ C2,
         int Nc, int K) {
    extern __shared__ __align__(16) half dynsm[];
    const half* W = Wh + (size_t)blockIdx.z * wStride;
    const float* bb = (blockIdx.z == 0) ? b0 : (blockIdx.z == 1) ? b1 : b2;
    half* C = (blockIdx.z == 0) ? C0 : (blockIdx.z == 1) ? C1 : C2;
    gemm_body2(A, W, bb, C, Nc, K, dynsm);
}

// ---------------------------------------------------------------------------
// Mask-compacted FP16 flash attention, double-buffered cp.async KV gather,
// Q fragments hoisted to registers. 1 head/block, static smem (47.1 KB).
// ---------------------------------------------------------------------------
#define ALQH 40
#define ALP  68
#define ALPH 72

__global__ void __launch_bounds__(128)
attn_tc(const __half* __restrict__ q,
        const __half* __restrict__ k,
        const __half* __restrict__ v,
        const int*    __restrict__ idxs,
        const int*    __restrict__ cnts,
        __half* __restrict__ att) {
    __shared__ __align__(16) half  Ks[2][64][ALQH];   // 10240 B
    __shared__ __align__(16) half  Vs[2][64][ALQH];   // 10240 B
    __shared__ __align__(16) float Ps[4][16][ALP];    // 17408 B
    __shared__ __align__(16) half  Ph[4][16][ALPH];   //  9216 B

    const int b = blockIdx.z, h = blockIdx.y;
    const int tid = threadIdx.x;
    const int warp = tid >> 5;
    const int lane = tid & 31;
    const int qrow0 = blockIdx.x * 64;
    const float sc2 = 0.17677669529663687f * 1.4426950408889634f;

    const int count = cnts[b];
    const int nTiles = (count + 63) >> 6;

    const int r = tid >> 1;
    const int c = (tid & 1) * 16;

    // stage Q through Ks[0], hoist fragments to registers
    {
        const __half* src = q + ((size_t)(b * Nn + qrow0 + r)) * Dn + h * DKn + c;
        *(uint4*)&Ks[0][r][c]     = *(const uint4*)(src);
        *(uint4*)&Ks[0][r][c + 8] = *(const uint4*)(src + 8);
    }
    __syncthreads();
    wmma::fragment<wmma::matrix_a, 16, 16, 16, half, wmma::row_major> qf[2];
    wmma::load_matrix_sync(qf[0], &Ks[0][warp * 16][0],  ALQH);
    wmma::load_matrix_sync(qf[1], &Ks[0][warp * 16][16], ALQH);
    __syncthreads();

    const uint32_t kbase = (uint32_t)__cvta_generic_to_shared(Ks);
    const uint32_t vbase = (uint32_t)__cvta_generic_to_shared(Vs);
    const uint32_t soff  = (uint32_t)(r * ALQH + c) * 2;   // byte offset within buf

    // prefetch tile 0 into buf 0
    {
        int g = r;
        int col = (g < count) ? idxs[b * Nn + g] : 0;
        size_t off = ((size_t)(b * Nn + col)) * Dn + h * DKn + c;
        cp16(kbase + soff,      k + off);
        cp16(kbase + soff + 16, k + off + 8);
        cp16(vbase + soff,      v + off);
        cp16(vbase + soff + 16, v + off + 8);
        cp_commit();
    }

    wmma::fragment<wmma::accumulator, 16, 16, 16, float> ao[2];
    wmma::fill_fragment(ao[0], 0.f);
    wmma::fill_fragment(ao[1], 0.f);

    float l_tot = 0.f;
    const int myrow = lane >> 1;
    const int colh = (lane & 1) * 32;
    const uint32_t bufB = (uint32_t)(64 * ALQH * 2);  // bytes per buffer

    for (int kt = 0; kt < nTiles; kt++) {
        const int buf = kt & 1;
        // prefetch next tile into buf^1
        if (kt + 1 < nTiles) {
            int g = (kt + 1) * 64 + r;
            int col = (g < count) ? idxs[b * Nn + g] : 0;
            size_t off = ((size_t)(b * Nn + col)) * Dn + h * DKn + c;
            uint32_t dst = (uint32_t)(buf ^ 1) * bufB + soff;
            cp16(kbase + dst,      k + off);
            cp16(kbase + dst + 16, k + off + 8);
            cp16(vbase + dst,      v + off);
            cp16(vbase + dst + 16, v + off + 8);
            cp_commit();
            cp_wait1();
        } else {
            cp_wait0();
        }
        __syncthreads();

        // S = Q @ K^T
        wmma::fragment<wmma::accumulator, 16, 16, 16, float> sf[4];
        #pragma unroll
        for (int n = 0; n < 4; n++) wmma::fill_fragment(sf[n], 0.f);
        #pragma unroll
        for (int ks = 0; ks < 2; ks++) {
            #pragma unroll
            for (int n = 0; n < 4; n++) {
                wmma::fragment<wmma::matrix_b, 16, 16, 16, half, wmma::col_major> bf;
                wmma::load_matrix_sync(bf, &Ks[buf][n * 16][ks * 16], ALQH);
                wmma::mma_sync(sf[n], qf[ks], bf, sf[n]);
            }
        }
        #pragma unroll
        for (int n = 0; n < 4; n++)
            wmma::store_matrix_sync(&Ps[warp][0][n * 16], sf[n], ALP, wmma::mem_row_major);
        __syncwarp();

        float lp = 0.f;
        const float* srow = &Ps[warp][myrow][colh];
        half* prow = &Ph[warp][myrow][colh];
        const int jbase = kt * 64 + colh;
        const int nvalid = count - jbase;
        #pragma unroll
        for (int j = 0; j < 32; j += 2) {
            float a0 = (j     < nvalid) ? srow[j]     * sc2 : -1e4f;
            float a1 = (j + 1 < nvalid) ? srow[j + 1] * sc2 : -1e4f;
            half2 p2 = h2exp2(__floats2half2_rn(a0, a1));
            *(half2*)(prow + j) = p2;
            float2 pf = __half22float2(p2);
            lp += pf.x + pf.y;
        }
        lp += __shfl_xor_sync(0xffffffffu, lp, 1);
        l_tot += lp;
        __syncwarp();

        #pragma unroll
        for (int ks = 0; ks < 4; ks++) {
            wmma::fragment<wmma::matrix_a, 16, 16, 16, half, wmma::row_major> af;
            wmma::load_matrix_sync(af, &Ph[warp][0][ks * 16], ALPH);
            #pragma unroll
            for (int n = 0; n < 2; n++) {
                wmma::fragment<wmma::matrix_b, 16, 16, 16, half, wmma::row_major> bf;
                wmma::load_matrix_sync(bf, &Vs[buf][ks * 16][n * 16], ALQH);
                wmma::mma_sync(ao[n], af, bf, ao[n]);
            }
        }
    }

    float* Os = &Ps[warp][0][0];
    wmma::store_matrix_sync(Os,      ao[0], ALP, wmma::mem_row_major);
    wmma::store_matrix_sync(Os + 16, ao[1], ALP, wmma::mem_row_major);
    __syncwarp();

    const float inv = 0.3f / l_tot;
    const int ch = (lane & 1) * 16;
    __half* orow = att + ((size_t)(b * Nn + qrow0 + warp * 16 + myrow)) * Dn + h * DKn + ch;
    float* sro = Os + myrow * ALP + ch;
    #pragma unroll
    for (int cc = 0; cc < 8; cc++) {
        half2 o2 = *(half2*)(orow + cc * 2);
        float2 of = __half22float2(o2);
        of.x += sro[cc * 2]     * inv;
        of.y += sro[cc * 2 + 1] * inv;
        *(half2*)(orow + cc * 2) = __floats2half2_rn(of.x, of.y);
    }
}

// ---------------------------------------------------------------------------
// Launch
// ---------------------------------------------------------------------------
extern "C" void kernel_launch(void* const* d_in, const int* in_sizes, int n_in,
                              void* d_out, int out_size) {
    const float* x_in  = (const float*)d_in[0];
    const int*   mask  = (const int*)  d_in[1];
    const float* adj   = (const float*)d_in[2];
    const float* dist  = (const float*)d_in[3];
    const float* Wq    = (const float*)d_in[5];
    const float* bq    = (const float*)d_in[6];
    const float* Wk    = (const float*)d_in[7];
    const float* bk    = (const float*)d_in[8];
    const float* Wv    = (const float*)d_in[9];
    const float* bv    = (const float*)d_in[10];
    const float* Wo    = (const float*)d_in[11];
    const float* bo    = (const float*)d_in[12];
    const float* Wf1   = (const float*)d_in[13];
    const float* bf1   = (const float*)d_in[14];
    const float* Wf2   = (const float*)d_in[15];
    const float* bf2   = (const float*)d_in[16];
    const float* ln1a  = (const float*)d_in[17];
    const float* ln1b  = (const float*)d_in[18];
    const float* ln2a  = (const float*)d_in[19];
    const float* ln2b  = (const float*)d_in[20];
    const float* lnfa  = (const float*)d_in[21];
    const float* lnfb  = (const float*)d_in[22];

    float *px;
    __half *pbaseh, *phh, *pqh, *pkh, *pvh, *pt1, *pph, *pwh;
    int *pidx, *pcnt;
    cudaGetSymbolAddress((void**)&px,     g_x);
    cudaGetSymbolAddress((void**)&pbaseh, g_baseh);
    cudaGetSymbolAddress((void**)&phh,    g_hh);
    cudaGetSymbolAddress((void**)&pqh,    g_qh);
    cudaGetSymbolAddress((void**)&pkh,    g_kh);
    cudaGetSymbolAddress((void**)&pvh,    g_vh);
    cudaGetSymbolAddress((void**)&pt1,    g_t1);
    cudaGetSymbolAddress((void**)&pph,    g_ph);
    cudaGetSymbolAddress((void**)&pwh,    g_wh);
    cudaGetSymbolAddress((void**)&pidx,   g_idx);
    cudaGetSymbolAddress((void**)&pcnt,   g_cnt);

    static bool attrDone = false;
    if (!attrDone) {
        cudaFuncSetAttribute(gemm_qkv, cudaFuncAttributeMaxDynamicSharedMemorySize, CA2_SMEM);
        attrDone = true;
    }

    cudaMemcpyAsync(px, x_in, sizeof(float) * BND, cudaMemcpyDeviceToDevice, 0);

    cvt_w<<<(6 * WSZ) / 1024, 256>>>(Wq, Wk, Wv, Wo, Wf1, Wf2, pwh);
    base_kernel<<<Bn * Nn, 256>>>(dist, adj, mask, pbaseh);
    mask_idx_kernel<<<Bn, 512>>>(mask, pidx, pcnt);

    const dim3 gProj(Dn / 128, (Bn * Nn) / 64, 1);    // 256 blocks (64x128 tile)
    const dim3 gQKV (Dn / 128, (Bn * Nn) / 128, 3);   // 384 blocks (128x128 tile)
    const dim3 gBaseV(Dn / 128, Nn / 64, Bn);         // 256 blocks
    const dim3 gAttn(Nn / 64, Hn, Bn);                // 1024 blocks
    const dim3 gLN(Bn * Nn / 8, 1, 1);

    for (int i = 0; i < Ln; i++) {
        const size_t wOff = (size_t)i * Dn * Dn;
        const size_t vOff = (size_t)i * Dn;

        ln_h<<<gLN, 256>>>(px, ln1a + vOff, ln1b + vOff, phh);

        gemm_qkv<<<gQKV, 256, CA2_SMEM>>>(phh, pwh + wOff, (long)WSZ,
                                          bq + vOff, bk + vOff, bv + vOff,
                                          pqh, pkh, pvh, Dn, Dn);

        // att = base @ V  (half, K=512, 64x128 tile, 256 blocks)
        gemm_hhz<<<gBaseV, 256>>>(pbaseh, pvh, pph, Dn, Nn,
                                  (long)Nn * Nn, (long)Nn * Dn, (long)Nn * Dn);

        // att += 0.3 * softmax @ V  (mask-compacted, pipelined gather)
        attn_tc<<<gAttn, 128>>>(pqh, pkh, pvh, pidx, pcnt, pph);

        // x = x + att @ Wo + bo  (64x128 tile, 256 blocks)
        gemm_hf<<<gProj, 256>>>(pph, pwh + 3 * WSZ + wOff, bo + vOff, px, px,
                                Dn, Dn, 0);

        // FFN (64x128 tile, 256 blocks)
        ln_h<<<gLN, 256>>>(px, ln2a + vOff, ln2b + vOff, phh);
        gemm_hh<<<gProj, 256>>>(phh, pwh + 4 * WSZ + wOff, bf1 + vOff, pt1,
                                Dn, Dn, 1);
        gemm_hf<<<gProj, 256>>>(pt1, pwh + 5 * WSZ + wOff, bf2 + vOff, px, px,
                                Dn, Dn, 1);
    }

    ln_f<<<gLN, 256>>>(px, lnfa, lnfb, (float*)d_out);
}